// round 12
// baseline (speedup 1.0000x reference)
#include <cuda_runtime.h>
#include <cuda_bf16.h>
#include <math.h>
#include <stdint.h>

// Problem constants: B=1, D=16, H=64, W=64, C=128, WS=8, SS=4, NH=4, hd=32
#define TOK   65536
#define CCH   128
#define NWIN  128
#define WN    512
#define NH    4
#define HD    32
#define MLPH  512

typedef __nv_bfloat16 bf16;

// Scratch
__device__ bf16     g_xw [TOK * CCH];
__device__ bf16     g_qkv[TOK * 384];
__device__ uint32_t g_rpe2[NH * WN * 256];   // packed bf16 pairs of exp(rpe)
__device__ bf16     g_ao [TOK * CCH];
__device__ float    g_y  [TOK * CCH];
__device__ bf16     g_h2 [TOK * CCH];
__device__ bf16     g_mlp[TOK * MLPH];
__device__ bf16     g_wq[384 * 128];
__device__ bf16     g_wp[128 * 128];
__device__ bf16     g_w1[512 * 128];
__device__ bf16     g_w2[128 * 512];
__device__ float    g_qb[384];

// ---------------------------------------------------------------------------
// Helpers
// ---------------------------------------------------------------------------
__device__ __forceinline__ uint32_t packbf(float lo, float hi) {
    uint32_t r;
    asm("cvt.rn.bf16x2.f32 %0, %1, %2;" : "=r"(r) : "f"(hi), "f"(lo));
    return r;
}
__device__ __forceinline__ float bflo(uint32_t u) { return __uint_as_float(u << 16); }
__device__ __forceinline__ float bfhi(uint32_t u) { return __uint_as_float(u & 0xffff0000u); }
__device__ __forceinline__ void mmabf(float* c, const uint32_t* a, const uint32_t* b) {
    asm volatile(
        "mma.sync.aligned.m16n8k16.row.col.f32.bf16.bf16.f32 "
        "{%0,%1,%2,%3},{%4,%5,%6,%7},{%8,%9},{%0,%1,%2,%3};"
        : "+f"(c[0]), "+f"(c[1]), "+f"(c[2]), "+f"(c[3])
        : "r"(a[0]), "r"(a[1]), "r"(a[2]), "r"(a[3]), "r"(b[0]), "r"(b[1]));
}
__device__ __forceinline__ void ldmx4(uint32_t* r, const void* p) {
    unsigned a = (unsigned)__cvta_generic_to_shared(p);
    asm volatile("ldmatrix.sync.aligned.m8n8.x4.shared.b16 {%0,%1,%2,%3}, [%4];"
        : "=r"(r[0]), "=r"(r[1]), "=r"(r[2]), "=r"(r[3]) : "r"(a));
}
__device__ __forceinline__ void ldmx4t(uint32_t* r, const void* p) {
    unsigned a = (unsigned)__cvta_generic_to_shared(p);
    asm volatile("ldmatrix.sync.aligned.m8n8.x4.trans.shared.b16 {%0,%1,%2,%3}, [%4];"
        : "=r"(r[0]), "=r"(r[1]), "=r"(r[2]), "=r"(r[3]) : "r"(a));
}
__device__ __forceinline__ void cpa16(void* dst, const void* src) {
    unsigned d = (unsigned)__cvta_generic_to_shared(dst);
    asm volatile("cp.async.cg.shared.global [%0], [%1], 16;" :: "r"(d), "l"(src));
}
#define CP_COMMIT() asm volatile("cp.async.commit_group;")
#define CP_WAIT(n)  asm volatile("cp.async.wait_group %0;" :: "n"(n))

// ---------------------------------------------------------------------------
// Fused prep: exp(rpe) packed-bf16 table + weight conversion (+ q scale fold)
// ---------------------------------------------------------------------------
__global__ void prep_kernel(const int* __restrict__ ri, const float* __restrict__ rb,
                            uint32_t* __restrict__ rpe2,
                            const float* __restrict__ wq, const float* __restrict__ wp,
                            const float* __restrict__ w1, const float* __restrict__ w2,
                            const float* __restrict__ qb,
                            bf16* __restrict__ oq, bf16* __restrict__ op,
                            bf16* __restrict__ o1, bf16* __restrict__ o2,
                            float* __restrict__ oqb)
{
    const float scale = 0.17677669529663687f;
    int i = blockIdx.x * 256 + threadIdx.x;
    if (i < 131072) {
        int r0 = ri[2 * i];
        int r1 = ri[2 * i + 1];
        #pragma unroll
        for (int h = 0; h < NH; h++)
            rpe2[h * 131072 + i] = packbf(__expf(rb[r0 * NH + h]),
                                          __expf(rb[r1 * NH + h]));
    }
    if (i < 384) oqb[i] = qb[i] * ((i < 128) ? scale : 1.f);
    if (i < 49152) {
        float v = wq[i] * (((i >> 7) < 128) ? scale : 1.f);
        oq[i] = __float2bfloat16(v);
    } else if (i < 65536)  op[i - 49152]  = __float2bfloat16(wp[i - 49152]);
    else if (i < 131072)   o1[i - 65536]  = __float2bfloat16(w1[i - 65536]);
    else if (i < 196608)   o2[i - 131072] = __float2bfloat16(w2[i - 131072]);
}

// ---------------------------------------------------------------------------
// LN1 + roll(-4,-4,-4) + window partition; bf16 out. One warp per token.
// ---------------------------------------------------------------------------
__global__ __launch_bounds__(256) void ln1_shift_kernel(
    const float* __restrict__ x, const float* __restrict__ g,
    const float* __restrict__ b, bf16* __restrict__ out)
{
    int m    = blockIdx.x * 8 + (threadIdx.x >> 5);
    int lane = threadIdx.x & 31;
    int win = m >> 9, nl = m & 511;
    int wd = win >> 6, wh = (win >> 3) & 7, ww = win & 7;
    int nd = nl >> 6,  nh = (nl >> 3) & 7,  nw = nl & 7;
    int d  = ((wd * 8 + nd) + 4) & 15;
    int hh = ((wh * 8 + nh) + 4) & 63;
    int w  = ((ww * 8 + nw) + 4) & 63;
    int t  = (d * 64 + hh) * 64 + w;

    float4 v = ((const float4*)(x + (size_t)t * CCH))[lane];
    float s  = v.x + v.y + v.z + v.w;
    float s2 = v.x * v.x + v.y * v.y + v.z * v.z + v.w * v.w;
    #pragma unroll
    for (int o = 16; o; o >>= 1) {
        s  += __shfl_xor_sync(0xffffffffu, s,  o);
        s2 += __shfl_xor_sync(0xffffffffu, s2, o);
    }
    float mean = s * (1.f / 128.f);
    float var  = s2 * (1.f / 128.f) - mean * mean;
    float inv  = rsqrtf(var + 1e-5f);
    float4 gg = ((const float4*)g)[lane];
    float4 bb = ((const float4*)b)[lane];
    uint32_t p0 = packbf((v.x - mean) * inv * gg.x + bb.x,
                         (v.y - mean) * inv * gg.y + bb.y);
    uint32_t p1 = packbf((v.z - mean) * inv * gg.z + bb.z,
                         (v.w - mean) * inv * gg.w + bb.w);
    *(uint2*)(out + (size_t)m * CCH + lane * 4) = make_uint2(p0, p1);
}

__global__ __launch_bounds__(256) void ln2_kernel(
    const float* __restrict__ x, const float* __restrict__ g,
    const float* __restrict__ b, bf16* __restrict__ out)
{
    int m    = blockIdx.x * 8 + (threadIdx.x >> 5);
    int lane = threadIdx.x & 31;
    float4 v = ((const float4*)(x + (size_t)m * CCH))[lane];
    float s  = v.x + v.y + v.z + v.w;
    float s2 = v.x * v.x + v.y * v.y + v.z * v.z + v.w * v.w;
    #pragma unroll
    for (int o = 16; o; o >>= 1) {
        s  += __shfl_xor_sync(0xffffffffu, s,  o);
        s2 += __shfl_xor_sync(0xffffffffu, s2, o);
    }
    float mean = s * (1.f / 128.f);
    float var  = s2 * (1.f / 128.f) - mean * mean;
    float inv  = rsqrtf(var + 1e-5f);
    float4 gg = ((const float4*)g)[lane];
    float4 bb = ((const float4*)b)[lane];
    uint32_t p0 = packbf((v.x - mean) * inv * gg.x + bb.x,
                         (v.y - mean) * inv * gg.y + bb.y);
    uint32_t p1 = packbf((v.z - mean) * inv * gg.z + bb.z,
                         (v.w - mean) * inv * gg.w + bb.w);
    *(uint2*)(out + (size_t)m * CCH + lane * 4) = make_uint2(p0, p1);
}

// ---------------------------------------------------------------------------
// bf16 GEMM (measured-best form): C[M,N] = A[M,K] @ B[N,K]^T + epilogue.
// ---------------------------------------------------------------------------
template <int MODE>
__global__ __launch_bounds__(256) void gemm_bf16(
    const bf16* __restrict__ A, const bf16* __restrict__ B,
    const float* __restrict__ bias, void* __restrict__ Cv,
    const float* __restrict__ R, int M, int N, int K)
{
    __shared__ bf16 As[2][128][40];
    __shared__ bf16 Bs[2][128][40];
    int tid = threadIdx.x, lane = tid & 31, warp = tid >> 5;
    int bm = blockIdx.x * 128, bn = blockIdx.y * 128;
    int wm = (warp >> 2) * 64, wn = (warp & 3) * 32;
    int r4 = lane >> 2, c4 = lane & 3;

    float acc[4][4][4];
    #pragma unroll
    for (int i = 0; i < 4; i++)
        #pragma unroll
        for (int j = 0; j < 4; j++)
            #pragma unroll
            for (int c = 0; c < 4; c++) acc[i][j][c] = 0.f;

    int lr = tid >> 1, lc = (tid & 1) * 16;
    const bf16* Ag = A + (size_t)(bm + lr) * K + lc;
    const bf16* Bg = B + (size_t)(bn + lr) * K + lc;

    cpa16(&As[0][lr][lc],     Ag);
    cpa16(&As[0][lr][lc + 8], Ag + 8);
    cpa16(&Bs[0][lr][lc],     Bg);
    cpa16(&Bs[0][lr][lc + 8], Bg + 8);
    CP_COMMIT();

    int niter = K >> 5;
    #pragma unroll 1
    for (int it = 0; it < niter; it++) {
        int cur = it & 1;
        if (it + 1 < niter) {
            int nxt = cur ^ 1;
            int kt = (it + 1) * 32;
            cpa16(&As[nxt][lr][lc],     Ag + kt);
            cpa16(&As[nxt][lr][lc + 8], Ag + kt + 8);
            cpa16(&Bs[nxt][lr][lc],     Bg + kt);
            cpa16(&Bs[nxt][lr][lc + 8], Bg + kt + 8);
            CP_COMMIT();
            CP_WAIT(1);
        } else {
            CP_WAIT(0);
        }
        __syncthreads();
        #pragma unroll
        for (int k16 = 0; k16 < 32; k16 += 16) {
            uint32_t af[4][4], bfr[4][2];
            #pragma unroll
            for (int i = 0; i < 4; i++) {
                int r = wm + 16 * i;
                af[i][0] = *(const uint32_t*)&As[cur][r +     r4][k16 + 2 * c4];
                af[i][1] = *(const uint32_t*)&As[cur][r + 8 + r4][k16 + 2 * c4];
                af[i][2] = *(const uint32_t*)&As[cur][r +     r4][k16 + 2 * c4 + 8];
                af[i][3] = *(const uint32_t*)&As[cur][r + 8 + r4][k16 + 2 * c4 + 8];
            }
            #pragma unroll
            for (int j = 0; j < 4; j++) {
                int c = wn + 8 * j;
                bfr[j][0] = *(const uint32_t*)&Bs[cur][c + r4][k16 + 2 * c4];
                bfr[j][1] = *(const uint32_t*)&Bs[cur][c + r4][k16 + 2 * c4 + 8];
            }
            #pragma unroll
            for (int i = 0; i < 4; i++)
                #pragma unroll
                for (int j = 0; j < 4; j++)
                    mmabf(acc[i][j], af[i], bfr[j]);
        }
        __syncthreads();
    }

    #pragma unroll
    for (int i = 0; i < 4; i++) {
        #pragma unroll
        for (int h = 0; h < 2; h++) {
            int m = bm + wm + 16 * i + r4 + 8 * h;
            size_t trow = m;
            if (MODE == 3) {
                int win = m >> 9, nl = m & 511;
                int wd = win >> 6, wh = (win >> 3) & 7, ww = win & 7;
                int nd = nl >> 6,  nh = (nl >> 3) & 7,  nw = nl & 7;
                int d  = ((wd * 8 + nd) + 4) & 15;
                int hh = ((wh * 8 + nh) + 4) & 63;
                int w  = ((ww * 8 + nw) + 4) & 63;
                trow = (size_t)((d * 64 + hh) * 64 + w);
            }
            #pragma unroll
            for (int j = 0; j < 4; j++) {
                int c0 = bn + wn + 8 * j + 2 * c4;
                float v0 = acc[i][j][2 * h + 0] + bias[c0];
                float v1 = acc[i][j][2 * h + 1] + bias[c0 + 1];
                if (MODE == 0) {
                    *(uint32_t*)((bf16*)Cv + (size_t)m * N + c0) = packbf(v0, v1);
                } else if (MODE == 1) {
                    float g0 = 0.5f * v0 * (1.0f + erff(v0 * 0.70710678118654752f));
                    float g1 = 0.5f * v1 * (1.0f + erff(v1 * 0.70710678118654752f));
                    *(uint32_t*)((bf16*)Cv + (size_t)m * N + c0) = packbf(g0, g1);
                } else if (MODE == 2) {
                    float2 rr = *(const float2*)(R + (size_t)m * N + c0);
                    *(float2*)((float*)Cv + (size_t)m * N + c0) =
                        make_float2(v0 + rr.x, v1 + rr.y);
                } else {
                    float2 rr = *(const float2*)(R + trow * CCH + c0);
                    *(float2*)((float*)Cv + trow * CCH + c0) =
                        make_float2(v0 + rr.x, v1 + rr.y);
                }
            }
        }
    }
}

// ---------------------------------------------------------------------------
// bf16 tensor-core attention: 32 q-rows per warp (2 m-tiles), K/V fragments
// reused across both m-tiles -> half the smem/L1 traffic per unit work.
// Block covers 256 q rows; grid (NH, NWIN, 2). 2 blocks/SM.
// ---------------------------------------------------------------------------
__global__ __launch_bounds__(256, 2) void attn_mma(
    const bf16* __restrict__ qkv, const uint32_t* __restrict__ rpe2,
    bf16* __restrict__ out)
{
    __shared__ bf16 Ks[2][64][40];
    __shared__ bf16 Vs[2][64][40];
    __shared__ unsigned char regtab[512];

    int head = blockIdx.x, win = blockIdx.y, qt = blockIdx.z;
    int tid = threadIdx.x, lane = tid & 31, warp = tid >> 5;
    int r4 = lane >> 2, c4 = lane & 3;

    int wd = win >> 6, wh = (win >> 3) & 7, ww = win & 7;
    bool masked_win = (wd == 1) || (wh == 7) || (ww == 7);
    if (masked_win) {
        for (int n = tid; n < 512; n += 256) {
            int nd = n >> 6, nh = (n >> 3) & 7, nw = n & 7;
            int rd = (wd == 1) ? ((nd < 4) ? 1 : 2) : 0;
            int rh = (wh == 7) ? ((nh < 4) ? 1 : 2) : 0;
            int rw = (ww == 7) ? ((nw < 4) ? 1 : 2) : 0;
            regtab[n] = (unsigned char)(rd * 9 + rh * 3 + rw);
        }
    }

    int qr = qt * 256 + warp * 32;
    uint32_t qf[2][2][4];    // [m-tile][k16][frag]
    #pragma unroll
    for (int mt = 0; mt < 2; mt++) {
        const bf16* qb = qkv + (size_t)(win * WN + qr + mt * 16) * 384 + head * HD;
        #pragma unroll
        for (int kb = 0; kb < 2; kb++) {
            qf[mt][kb][0] = *(const uint32_t*)(qb + (size_t)r4       * 384 + kb * 16 + 2 * c4);
            qf[mt][kb][1] = *(const uint32_t*)(qb + (size_t)(r4 + 8) * 384 + kb * 16 + 2 * c4);
            qf[mt][kb][2] = *(const uint32_t*)(qb + (size_t)r4       * 384 + kb * 16 + 2 * c4 + 8);
            qf[mt][kb][3] = *(const uint32_t*)(qb + (size_t)(r4 + 8) * 384 + kb * 16 + 2 * c4 + 8);
        }
    }

    float o[2][4][4];
    #pragma unroll
    for (int mt = 0; mt < 2; mt++)
        #pragma unroll
        for (int j = 0; j < 4; j++)
            #pragma unroll
            for (int c = 0; c < 4; c++) o[mt][j][c] = 0.f;
    float l0[2] = {0.f, 0.f}, l1[2] = {0.f, 0.f};

    __syncthreads();
    int rr0[2], rr1[2];
    #pragma unroll
    for (int mt = 0; mt < 2; mt++) {
        rr0[mt] = 0; rr1[mt] = 0;
        if (masked_win) {
            rr0[mt] = regtab[qr + mt * 16 + r4];
            rr1[mt] = regtab[qr + mt * 16 + r4 + 8];
        }
    }
    const uint32_t* rpbase = rpe2 + ((size_t)head << 17) + c4;

    int ldrow = tid >> 2, ldsg = (tid & 3) * 8;
    int krow = (lane & 7) + 8 * ((lane >> 4) & 1);
    int kcol = ((lane >> 3) & 1) * 8;
    int vrow = (lane & 7) + ((lane >> 3) & 1) * 8;
    int vcol8 = ((lane >> 4) & 1) * 8;

    {
        const bf16* kbp = qkv + (size_t)(win * WN + ldrow) * 384 + 128 + head * HD + ldsg;
        cpa16(&Ks[0][ldrow][ldsg], kbp);
        cpa16(&Vs[0][ldrow][ldsg], kbp + 128);
        CP_COMMIT();
    }

    #pragma unroll 1
    for (int ci = 0; ci < 8; ci++) {
        int cur = ci & 1;
        if (ci + 1 < 8) {
            int nxt = cur ^ 1;
            const bf16* kbp = qkv + (size_t)(win * WN + (ci + 1) * 64 + ldrow) * 384
                              + 128 + head * HD + ldsg;
            cpa16(&Ks[nxt][ldrow][ldsg], kbp);
            cpa16(&Vs[nxt][ldrow][ldsg], kbp + 128);
            CP_COMMIT();
            CP_WAIT(1);
        } else {
            CP_WAIT(0);
        }
        __syncthreads();
        int c0 = ci * 64;

        #pragma unroll
        for (int kb = 0; kb < 4; kb++) {
            uint32_t kf0[4], kf1[4];
            ldmx4(kf0, &Ks[cur][16 * kb + krow][kcol]);
            ldmx4(kf1, &Ks[cur][16 * kb + krow][16 + kcol]);

            uint32_t pa[2][4];
            #pragma unroll
            for (int mt = 0; mt < 2; mt++) {
                float s8[8];
                #pragma unroll
                for (int c = 0; c < 8; c++) s8[c] = 0.f;
                mmabf(s8,     qf[mt][0], kf0);
                mmabf(s8 + 4, qf[mt][0], kf0 + 2);
                mmabf(s8,     qf[mt][1], kf1);
                mmabf(s8 + 4, qf[mt][1], kf1 + 2);

                #pragma unroll
                for (int half = 0; half < 2; half++) {
                    int nj = 2 * kb + half;
                    float* s4 = s8 + 4 * half;
                    uint32_t u0 = rpbase[(size_t)(qr + mt * 16 + r4)     * 256 + ci * 32 + nj * 4];
                    uint32_t u1 = rpbase[(size_t)(qr + mt * 16 + r4 + 8) * 256 + ci * 32 + nj * 4];
                    float e00 = __expf(s4[0]) * bflo(u0);
                    float e01 = __expf(s4[1]) * bfhi(u0);
                    float e10 = __expf(s4[2]) * bflo(u1);
                    float e11 = __expf(s4[3]) * bfhi(u1);
                    if (masked_win) {
                        int cc = c0 + nj * 8 + 2 * c4;
                        int rc0 = regtab[cc], rc1 = regtab[cc + 1];
                        e00 = (rr0[mt] == rc0) ? e00 : 0.f;
                        e01 = (rr0[mt] == rc1) ? e01 : 0.f;
                        e10 = (rr1[mt] == rc0) ? e10 : 0.f;
                        e11 = (rr1[mt] == rc1) ? e11 : 0.f;
                    }
                    l0[mt] += e00 + e01;
                    l1[mt] += e10 + e11;
                    pa[mt][2 * half + 0] = packbf(e00, e01);
                    pa[mt][2 * half + 1] = packbf(e10, e11);
                }
            }

            uint32_t vb[8];
            ldmx4t(vb,     &Vs[cur][kb * 16 + vrow][vcol8]);
            ldmx4t(vb + 4, &Vs[cur][kb * 16 + vrow][16 + vcol8]);
            #pragma unroll
            for (int mt = 0; mt < 2; mt++) {
                mmabf(o[mt][0], pa[mt], vb);
                mmabf(o[mt][1], pa[mt], vb + 2);
                mmabf(o[mt][2], pa[mt], vb + 4);
                mmabf(o[mt][3], pa[mt], vb + 6);
            }
        }
        __syncthreads();
    }

    #pragma unroll
    for (int mt = 0; mt < 2; mt++) {
        float a = l0[mt], b = l1[mt];
        a += __shfl_xor_sync(0xffffffffu, a, 1);
        a += __shfl_xor_sync(0xffffffffu, a, 2);
        b += __shfl_xor_sync(0xffffffffu, b, 1);
        b += __shfl_xor_sync(0xffffffffu, b, 2);
        float i0 = 1.f / a, i1 = 1.f / b;
        bf16* ob = out + (size_t)(win * WN + qr + mt * 16) * CCH + head * HD;
        #pragma unroll
        for (int dj = 0; dj < 4; dj++) {
            *(uint32_t*)(ob + (size_t)r4       * CCH + dj * 8 + 2 * c4) =
                packbf(o[mt][dj][0] * i0, o[mt][dj][1] * i0);
            *(uint32_t*)(ob + (size_t)(r4 + 8) * CCH + dj * 8 + 2 * c4) =
                packbf(o[mt][dj][2] * i1, o[mt][dj][3] * i1);
        }
    }
}

// ---------------------------------------------------------------------------
extern "C" void kernel_launch(void* const* d_in, const int* in_sizes, int n_in,
                              void* d_out, int out_size)
{
    const float* x         = (const float*)d_in[0];
    const int*   rel_index = (const int*)  d_in[2];
    const float* rel_bias  = (const float*)d_in[3];
    const float* qkv_w     = (const float*)d_in[4];
    const float* qkv_b     = (const float*)d_in[5];
    const float* proj_w    = (const float*)d_in[6];
    const float* proj_b    = (const float*)d_in[7];
    const float* n1g       = (const float*)d_in[8];
    const float* n1b       = (const float*)d_in[9];
    const float* n2g       = (const float*)d_in[10];
    const float* n2b       = (const float*)d_in[11];
    const float* w1        = (const float*)d_in[12];
    const float* b1        = (const float*)d_in[13];
    const float* w2        = (const float*)d_in[14];
    const float* b2        = (const float*)d_in[15];
    float* out = (float*)d_out;

    bf16 *xw, *qkv, *ao, *h2, *mlp, *wq, *wp, *ww1, *ww2;
    float *y, *qb;
    uint32_t *rpe2;
    cudaGetSymbolAddress((void**)&xw,   g_xw);
    cudaGetSymbolAddress((void**)&qkv,  g_qkv);
    cudaGetSymbolAddress((void**)&rpe2, g_rpe2);
    cudaGetSymbolAddress((void**)&ao,   g_ao);
    cudaGetSymbolAddress((void**)&y,    g_y);
    cudaGetSymbolAddress((void**)&h2,   g_h2);
    cudaGetSymbolAddress((void**)&mlp,  g_mlp);
    cudaGetSymbolAddress((void**)&wq,   g_wq);
    cudaGetSymbolAddress((void**)&wp,   g_wp);
    cudaGetSymbolAddress((void**)&ww1,  g_w1);
    cudaGetSymbolAddress((void**)&ww2,  g_w2);
    cudaGetSymbolAddress((void**)&qb,   g_qb);

    prep_kernel<<<1024, 256>>>(rel_index, rel_bias, rpe2,
                               qkv_w, proj_w, w1, w2, qkv_b,
                               wq, wp, ww1, ww2, qb);
    ln1_shift_kernel<<<TOK / 8, 256>>>(x, n1g, n1b, xw);
    gemm_bf16<0><<<dim3(TOK / 128, 3), 256>>>(xw, wq, qb, qkv, nullptr,
                                              TOK, 384, 128);
    attn_mma<<<dim3(NH, NWIN, 2), 256>>>(qkv, rpe2, ao);
    gemm_bf16<3><<<dim3(TOK / 128, 1), 256>>>(ao, wp, proj_b, y, x,
                                              TOK, 128, 128);
    ln2_kernel<<<TOK / 8, 256>>>(y, n2g, n2b, h2);
    gemm_bf16<1><<<dim3(TOK / 128, 4), 256>>>(h2, ww1, b1, mlp, nullptr,
                                              TOK, 512, 128);
    gemm_bf16<2><<<dim3(TOK / 128, 1), 256>>>(mlp, ww2, b2, out, y,
                                              TOK, 128, 512);
}

// round 13
// speedup vs baseline: 1.3052x; 1.3052x over previous
#include <cuda_runtime.h>
#include <cuda_bf16.h>
#include <math.h>
#include <stdint.h>

// Problem constants: B=1, D=16, H=64, W=64, C=128, WS=8, SS=4, NH=4, hd=32
#define TOK   65536
#define CCH   128
#define NWIN  128
#define WN    512
#define NH    4
#define HD    32
#define MLPH  512

typedef __nv_bfloat16 bf16;

// Scratch
__device__ bf16     g_xw [TOK * CCH];
__device__ bf16     g_qkv[TOK * 384];
__device__ uint32_t g_rpe2[NH * WN * 256];   // packed bf16 pairs of exp(rpe)
__device__ bf16     g_ao [TOK * CCH];
__device__ float    g_y  [TOK * CCH];
__device__ bf16     g_h2 [TOK * CCH];
__device__ bf16     g_mlp[TOK * MLPH];
__device__ bf16     g_wq[384 * 128];
__device__ bf16     g_wp[128 * 128];
__device__ bf16     g_w1[512 * 128];
__device__ bf16     g_w2[128 * 512];
__device__ float    g_qb[384];

// ---------------------------------------------------------------------------
// Helpers
// ---------------------------------------------------------------------------
__device__ __forceinline__ uint32_t packbf(float lo, float hi) {
    uint32_t r;
    asm("cvt.rn.bf16x2.f32 %0, %1, %2;" : "=r"(r) : "f"(hi), "f"(lo));
    return r;
}
__device__ __forceinline__ float bflo(uint32_t u) { return __uint_as_float(u << 16); }
__device__ __forceinline__ float bfhi(uint32_t u) { return __uint_as_float(u & 0xffff0000u); }
__device__ __forceinline__ void mmabf(float* c, const uint32_t* a, const uint32_t* b) {
    asm volatile(
        "mma.sync.aligned.m16n8k16.row.col.f32.bf16.bf16.f32 "
        "{%0,%1,%2,%3},{%4,%5,%6,%7},{%8,%9},{%0,%1,%2,%3};"
        : "+f"(c[0]), "+f"(c[1]), "+f"(c[2]), "+f"(c[3])
        : "r"(a[0]), "r"(a[1]), "r"(a[2]), "r"(a[3]), "r"(b[0]), "r"(b[1]));
}
__device__ __forceinline__ void ldmx4(uint32_t* r, const void* p) {
    unsigned a = (unsigned)__cvta_generic_to_shared(p);
    asm volatile("ldmatrix.sync.aligned.m8n8.x4.shared.b16 {%0,%1,%2,%3}, [%4];"
        : "=r"(r[0]), "=r"(r[1]), "=r"(r[2]), "=r"(r[3]) : "r"(a));
}
__device__ __forceinline__ void ldmx4t(uint32_t* r, const void* p) {
    unsigned a = (unsigned)__cvta_generic_to_shared(p);
    asm volatile("ldmatrix.sync.aligned.m8n8.x4.trans.shared.b16 {%0,%1,%2,%3}, [%4];"
        : "=r"(r[0]), "=r"(r[1]), "=r"(r[2]), "=r"(r[3]) : "r"(a));
}
__device__ __forceinline__ void cpa16(void* dst, const void* src) {
    unsigned d = (unsigned)__cvta_generic_to_shared(dst);
    asm volatile("cp.async.cg.shared.global [%0], [%1], 16;" :: "r"(d), "l"(src));
}
#define CP_COMMIT() asm volatile("cp.async.commit_group;")
#define CP_WAIT(n)  asm volatile("cp.async.wait_group %0;" :: "n"(n))

// ---------------------------------------------------------------------------
// Fused prep: exp(rpe) packed-bf16 table + weight conversion (+ q scale fold)
// ---------------------------------------------------------------------------
__global__ void prep_kernel(const int* __restrict__ ri, const float* __restrict__ rb,
                            uint32_t* __restrict__ rpe2,
                            const float* __restrict__ wq, const float* __restrict__ wp,
                            const float* __restrict__ w1, const float* __restrict__ w2,
                            const float* __restrict__ qb,
                            bf16* __restrict__ oq, bf16* __restrict__ op,
                            bf16* __restrict__ o1, bf16* __restrict__ o2,
                            float* __restrict__ oqb)
{
    const float scale = 0.17677669529663687f;
    int i = blockIdx.x * 256 + threadIdx.x;
    if (i < 131072) {
        int r0 = ri[2 * i];
        int r1 = ri[2 * i + 1];
        #pragma unroll
        for (int h = 0; h < NH; h++)
            rpe2[h * 131072 + i] = packbf(__expf(rb[r0 * NH + h]),
                                          __expf(rb[r1 * NH + h]));
    }
    if (i < 384) oqb[i] = qb[i] * ((i < 128) ? scale : 1.f);
    if (i < 49152) {
        float v = wq[i] * (((i >> 7) < 128) ? scale : 1.f);
        oq[i] = __float2bfloat16(v);
    } else if (i < 65536)  op[i - 49152]  = __float2bfloat16(wp[i - 49152]);
    else if (i < 131072)   o1[i - 65536]  = __float2bfloat16(w1[i - 65536]);
    else if (i < 196608)   o2[i - 131072] = __float2bfloat16(w2[i - 131072]);
}

// ---------------------------------------------------------------------------
// LN1 + roll(-4,-4,-4) + window partition; bf16 out. One warp per token.
// ---------------------------------------------------------------------------
__global__ __launch_bounds__(256) void ln1_shift_kernel(
    const float* __restrict__ x, const float* __restrict__ g,
    const float* __restrict__ b, bf16* __restrict__ out)
{
    int m    = blockIdx.x * 8 + (threadIdx.x >> 5);
    int lane = threadIdx.x & 31;
    int win = m >> 9, nl = m & 511;
    int wd = win >> 6, wh = (win >> 3) & 7, ww = win & 7;
    int nd = nl >> 6,  nh = (nl >> 3) & 7,  nw = nl & 7;
    int d  = ((wd * 8 + nd) + 4) & 15;
    int hh = ((wh * 8 + nh) + 4) & 63;
    int w  = ((ww * 8 + nw) + 4) & 63;
    int t  = (d * 64 + hh) * 64 + w;

    float4 v = ((const float4*)(x + (size_t)t * CCH))[lane];
    float s  = v.x + v.y + v.z + v.w;
    float s2 = v.x * v.x + v.y * v.y + v.z * v.z + v.w * v.w;
    #pragma unroll
    for (int o = 16; o; o >>= 1) {
        s  += __shfl_xor_sync(0xffffffffu, s,  o);
        s2 += __shfl_xor_sync(0xffffffffu, s2, o);
    }
    float mean = s * (1.f / 128.f);
    float var  = s2 * (1.f / 128.f) - mean * mean;
    float inv  = rsqrtf(var + 1e-5f);
    float4 gg = ((const float4*)g)[lane];
    float4 bb = ((const float4*)b)[lane];
    uint32_t p0 = packbf((v.x - mean) * inv * gg.x + bb.x,
                         (v.y - mean) * inv * gg.y + bb.y);
    uint32_t p1 = packbf((v.z - mean) * inv * gg.z + bb.z,
                         (v.w - mean) * inv * gg.w + bb.w);
    *(uint2*)(out + (size_t)m * CCH + lane * 4) = make_uint2(p0, p1);
}

__global__ __launch_bounds__(256) void ln2_kernel(
    const float* __restrict__ x, const float* __restrict__ g,
    const float* __restrict__ b, bf16* __restrict__ out)
{
    int m    = blockIdx.x * 8 + (threadIdx.x >> 5);
    int lane = threadIdx.x & 31;
    float4 v = ((const float4*)(x + (size_t)m * CCH))[lane];
    float s  = v.x + v.y + v.z + v.w;
    float s2 = v.x * v.x + v.y * v.y + v.z * v.z + v.w * v.w;
    #pragma unroll
    for (int o = 16; o; o >>= 1) {
        s  += __shfl_xor_sync(0xffffffffu, s,  o);
        s2 += __shfl_xor_sync(0xffffffffu, s2, o);
    }
    float mean = s * (1.f / 128.f);
    float var  = s2 * (1.f / 128.f) - mean * mean;
    float inv  = rsqrtf(var + 1e-5f);
    float4 gg = ((const float4*)g)[lane];
    float4 bb = ((const float4*)b)[lane];
    uint32_t p0 = packbf((v.x - mean) * inv * gg.x + bb.x,
                         (v.y - mean) * inv * gg.y + bb.y);
    uint32_t p1 = packbf((v.z - mean) * inv * gg.z + bb.z,
                         (v.w - mean) * inv * gg.w + bb.w);
    *(uint2*)(out + (size_t)m * CCH + lane * 4) = make_uint2(p0, p1);
}

// ---------------------------------------------------------------------------
// bf16 GEMM: C[M,N] = A[M,K] @ B[N,K]^T + epilogue.
// R13 experiment: __launch_bounds__(256, 3) -> cap regs ~84 for 3 blocks/SM.
// ---------------------------------------------------------------------------
template <int MODE>
__global__ __launch_bounds__(256, 3) void gemm_bf16(
    const bf16* __restrict__ A, const bf16* __restrict__ B,
    const float* __restrict__ bias, void* __restrict__ Cv,
    const float* __restrict__ R, int M, int N, int K)
{
    __shared__ bf16 As[2][128][40];
    __shared__ bf16 Bs[2][128][40];
    int tid = threadIdx.x, lane = tid & 31, warp = tid >> 5;
    int bm = blockIdx.x * 128, bn = blockIdx.y * 128;
    int wm = (warp >> 2) * 64, wn = (warp & 3) * 32;
    int r4 = lane >> 2, c4 = lane & 3;

    float acc[4][4][4];
    #pragma unroll
    for (int i = 0; i < 4; i++)
        #pragma unroll
        for (int j = 0; j < 4; j++)
            #pragma unroll
            for (int c = 0; c < 4; c++) acc[i][j][c] = 0.f;

    int lr = tid >> 1, lc = (tid & 1) * 16;
    const bf16* Ag = A + (size_t)(bm + lr) * K + lc;
    const bf16* Bg = B + (size_t)(bn + lr) * K + lc;

    cpa16(&As[0][lr][lc],     Ag);
    cpa16(&As[0][lr][lc + 8], Ag + 8);
    cpa16(&Bs[0][lr][lc],     Bg);
    cpa16(&Bs[0][lr][lc + 8], Bg + 8);
    CP_COMMIT();

    int niter = K >> 5;
    #pragma unroll 1
    for (int it = 0; it < niter; it++) {
        int cur = it & 1;
        if (it + 1 < niter) {
            int nxt = cur ^ 1;
            int kt = (it + 1) * 32;
            cpa16(&As[nxt][lr][lc],     Ag + kt);
            cpa16(&As[nxt][lr][lc + 8], Ag + kt + 8);
            cpa16(&Bs[nxt][lr][lc],     Bg + kt);
            cpa16(&Bs[nxt][lr][lc + 8], Bg + kt + 8);
            CP_COMMIT();
            CP_WAIT(1);
        } else {
            CP_WAIT(0);
        }
        __syncthreads();
        #pragma unroll
        for (int k16 = 0; k16 < 32; k16 += 16) {
            uint32_t af[4][4], bfr[4][2];
            #pragma unroll
            for (int i = 0; i < 4; i++) {
                int r = wm + 16 * i;
                af[i][0] = *(const uint32_t*)&As[cur][r +     r4][k16 + 2 * c4];
                af[i][1] = *(const uint32_t*)&As[cur][r + 8 + r4][k16 + 2 * c4];
                af[i][2] = *(const uint32_t*)&As[cur][r +     r4][k16 + 2 * c4 + 8];
                af[i][3] = *(const uint32_t*)&As[cur][r + 8 + r4][k16 + 2 * c4 + 8];
            }
            #pragma unroll
            for (int j = 0; j < 4; j++) {
                int c = wn + 8 * j;
                bfr[j][0] = *(const uint32_t*)&Bs[cur][c + r4][k16 + 2 * c4];
                bfr[j][1] = *(const uint32_t*)&Bs[cur][c + r4][k16 + 2 * c4 + 8];
            }
            #pragma unroll
            for (int i = 0; i < 4; i++)
                #pragma unroll
                for (int j = 0; j < 4; j++)
                    mmabf(acc[i][j], af[i], bfr[j]);
        }
        __syncthreads();
    }

    #pragma unroll
    for (int i = 0; i < 4; i++) {
        #pragma unroll
        for (int h = 0; h < 2; h++) {
            int m = bm + wm + 16 * i + r4 + 8 * h;
            size_t trow = m;
            if (MODE == 3) {
                int win = m >> 9, nl = m & 511;
                int wd = win >> 6, wh = (win >> 3) & 7, ww = win & 7;
                int nd = nl >> 6,  nh = (nl >> 3) & 7,  nw = nl & 7;
                int d  = ((wd * 8 + nd) + 4) & 15;
                int hh = ((wh * 8 + nh) + 4) & 63;
                int w  = ((ww * 8 + nw) + 4) & 63;
                trow = (size_t)((d * 64 + hh) * 64 + w);
            }
            #pragma unroll
            for (int j = 0; j < 4; j++) {
                int c0 = bn + wn + 8 * j + 2 * c4;
                float v0 = acc[i][j][2 * h + 0] + bias[c0];
                float v1 = acc[i][j][2 * h + 1] + bias[c0 + 1];
                if (MODE == 0) {
                    *(uint32_t*)((bf16*)Cv + (size_t)m * N + c0) = packbf(v0, v1);
                } else if (MODE == 1) {
                    float g0 = 0.5f * v0 * (1.0f + erff(v0 * 0.70710678118654752f));
                    float g1 = 0.5f * v1 * (1.0f + erff(v1 * 0.70710678118654752f));
                    *(uint32_t*)((bf16*)Cv + (size_t)m * N + c0) = packbf(g0, g1);
                } else if (MODE == 2) {
                    float2 rr = *(const float2*)(R + (size_t)m * N + c0);
                    *(float2*)((float*)Cv + (size_t)m * N + c0) =
                        make_float2(v0 + rr.x, v1 + rr.y);
                } else {
                    float2 rr = *(const float2*)(R + trow * CCH + c0);
                    *(float2*)((float*)Cv + trow * CCH + c0) =
                        make_float2(v0 + rr.x, v1 + rr.y);
                }
            }
        }
    }
}

// ---------------------------------------------------------------------------
// bf16 tensor-core attention (R11 measured-best): 3 blocks/SM, ldmatrix K,
// packed-bf16 exp(rpe) multiplies (exp(s+r) = exp(s)*er).
// ---------------------------------------------------------------------------
__global__ __launch_bounds__(256, 3) void attn_mma(
    const bf16* __restrict__ qkv, const uint32_t* __restrict__ rpe2,
    bf16* __restrict__ out)
{
    __shared__ bf16 Ks[2][64][40];
    __shared__ bf16 Vs[2][64][40];
    __shared__ unsigned char regtab[512];

    int head = blockIdx.x, win = blockIdx.y, qt = blockIdx.z;
    int tid = threadIdx.x, lane = tid & 31, warp = tid >> 5;
    int r4 = lane >> 2, c4 = lane & 3;

    int wd = win >> 6, wh = (win >> 3) & 7, ww = win & 7;
    bool masked_win = (wd == 1) || (wh == 7) || (ww == 7);
    if (masked_win) {
        for (int n = tid; n < 512; n += 256) {
            int nd = n >> 6, nh = (n >> 3) & 7, nw = n & 7;
            int rd = (wd == 1) ? ((nd < 4) ? 1 : 2) : 0;
            int rh = (wh == 7) ? ((nh < 4) ? 1 : 2) : 0;
            int rw = (ww == 7) ? ((nw < 4) ? 1 : 2) : 0;
            regtab[n] = (unsigned char)(rd * 9 + rh * 3 + rw);
        }
    }

    int qr = qt * 128 + warp * 16;
    const bf16* qb = qkv + (size_t)(win * WN + qr) * 384 + head * HD;
    uint32_t qf[2][4];
    #pragma unroll
    for (int kb = 0; kb < 2; kb++) {
        qf[kb][0] = *(const uint32_t*)(qb + (size_t)r4       * 384 + kb * 16 + 2 * c4);
        qf[kb][1] = *(const uint32_t*)(qb + (size_t)(r4 + 8) * 384 + kb * 16 + 2 * c4);
        qf[kb][2] = *(const uint32_t*)(qb + (size_t)r4       * 384 + kb * 16 + 2 * c4 + 8);
        qf[kb][3] = *(const uint32_t*)(qb + (size_t)(r4 + 8) * 384 + kb * 16 + 2 * c4 + 8);
    }

    float o[4][4];
    #pragma unroll
    for (int j = 0; j < 4; j++)
        #pragma unroll
        for (int c = 0; c < 4; c++) o[j][c] = 0.f;
    float l0 = 0.f, l1 = 0.f;

    __syncthreads();
    int row0 = qr + r4, row1 = row0 + 8;
    int rr0 = 0, rr1 = 0;
    if (masked_win) { rr0 = regtab[row0]; rr1 = regtab[row1]; }
    const uint32_t* rp0 = rpe2 + ((size_t)head << 17) + (size_t)row0 * 256 + c4;
    const uint32_t* rp1 = rpe2 + ((size_t)head << 17) + (size_t)row1 * 256 + c4;

    int ldrow = tid >> 2, ldsg = (tid & 3) * 8;
    int krow = (lane & 7) + 8 * ((lane >> 4) & 1);
    int kcol = ((lane >> 3) & 1) * 8;
    int vrow = (lane & 7) + ((lane >> 3) & 1) * 8;
    int vcol8 = ((lane >> 4) & 1) * 8;

    {
        const bf16* kbp = qkv + (size_t)(win * WN + ldrow) * 384 + 128 + head * HD + ldsg;
        cpa16(&Ks[0][ldrow][ldsg], kbp);
        cpa16(&Vs[0][ldrow][ldsg], kbp + 128);
        CP_COMMIT();
    }

    #pragma unroll 1
    for (int ci = 0; ci < 8; ci++) {
        int cur = ci & 1;
        if (ci + 1 < 8) {
            int nxt = cur ^ 1;
            const bf16* kbp = qkv + (size_t)(win * WN + (ci + 1) * 64 + ldrow) * 384
                              + 128 + head * HD + ldsg;
            cpa16(&Ks[nxt][ldrow][ldsg], kbp);
            cpa16(&Vs[nxt][ldrow][ldsg], kbp + 128);
            CP_COMMIT();
            CP_WAIT(1);
        } else {
            CP_WAIT(0);
        }
        __syncthreads();
        int c0 = ci * 64;

        #pragma unroll
        for (int kb = 0; kb < 4; kb++) {
            float s8[8];
            #pragma unroll
            for (int c = 0; c < 8; c++) s8[c] = 0.f;
            #pragma unroll
            for (int kq = 0; kq < 2; kq++) {
                uint32_t kf[4];
                ldmx4(kf, &Ks[cur][16 * kb + krow][kq * 16 + kcol]);
                mmabf(s8,     qf[kq], kf);
                mmabf(s8 + 4, qf[kq], kf + 2);
            }

            uint32_t pa[4];
            #pragma unroll
            for (int half = 0; half < 2; half++) {
                int nj = 2 * kb + half;
                float* s4 = s8 + 4 * half;
                uint32_t u0 = rp0[ci * 32 + nj * 4];
                uint32_t u1 = rp1[ci * 32 + nj * 4];
                float e00 = __expf(s4[0]) * bflo(u0);
                float e01 = __expf(s4[1]) * bfhi(u0);
                float e10 = __expf(s4[2]) * bflo(u1);
                float e11 = __expf(s4[3]) * bfhi(u1);
                if (masked_win) {
                    int cc = c0 + nj * 8 + 2 * c4;
                    int rc0 = regtab[cc], rc1 = regtab[cc + 1];
                    e00 = (rr0 == rc0) ? e00 : 0.f;
                    e01 = (rr0 == rc1) ? e01 : 0.f;
                    e10 = (rr1 == rc0) ? e10 : 0.f;
                    e11 = (rr1 == rc1) ? e11 : 0.f;
                }
                l0 += e00 + e01;
                l1 += e10 + e11;
                pa[2 * half + 0] = packbf(e00, e01);
                pa[2 * half + 1] = packbf(e10, e11);
            }

            uint32_t vb[8];
            ldmx4t(vb,     &Vs[cur][kb * 16 + vrow][vcol8]);
            ldmx4t(vb + 4, &Vs[cur][kb * 16 + vrow][16 + vcol8]);
            mmabf(o[0], pa, vb);
            mmabf(o[1], pa, vb + 2);
            mmabf(o[2], pa, vb + 4);
            mmabf(o[3], pa, vb + 6);
        }
        __syncthreads();
    }

    l0 += __shfl_xor_sync(0xffffffffu, l0, 1);
    l0 += __shfl_xor_sync(0xffffffffu, l0, 2);
    l1 += __shfl_xor_sync(0xffffffffu, l1, 1);
    l1 += __shfl_xor_sync(0xffffffffu, l1, 2);
    float i0 = 1.f / l0, i1 = 1.f / l1;

    bf16* ob = out + (size_t)(win * WN + qr) * CCH + head * HD;
    #pragma unroll
    for (int dj = 0; dj < 4; dj++) {
        *(uint32_t*)(ob + (size_t)r4       * CCH + dj * 8 + 2 * c4) =
            packbf(o[dj][0] * i0, o[dj][1] * i0);
        *(uint32_t*)(ob + (size_t)(r4 + 8) * CCH + dj * 8 + 2 * c4) =
            packbf(o[dj][2] * i1, o[dj][3] * i1);
    }
}

// ---------------------------------------------------------------------------
extern "C" void kernel_launch(void* const* d_in, const int* in_sizes, int n_in,
                              void* d_out, int out_size)
{
    const float* x         = (const float*)d_in[0];
    const int*   rel_index = (const int*)  d_in[2];
    const float* rel_bias  = (const float*)d_in[3];
    const float* qkv_w     = (const float*)d_in[4];
    const float* qkv_b     = (const float*)d_in[5];
    const float* proj_w    = (const float*)d_in[6];
    const float* proj_b    = (const float*)d_in[7];
    const float* n1g       = (const float*)d_in[8];
    const float* n1b       = (const float*)d_in[9];
    const float* n2g       = (const float*)d_in[10];
    const float* n2b       = (const float*)d_in[11];
    const float* w1        = (const float*)d_in[12];
    const float* b1        = (const float*)d_in[13];
    const float* w2        = (const float*)d_in[14];
    const float* b2        = (const float*)d_in[15];
    float* out = (float*)d_out;

    bf16 *xw, *qkv, *ao, *h2, *mlp, *wq, *wp, *ww1, *ww2;
    float *y, *qb;
    uint32_t *rpe2;
    cudaGetSymbolAddress((void**)&xw,   g_xw);
    cudaGetSymbolAddress((void**)&qkv,  g_qkv);
    cudaGetSymbolAddress((void**)&rpe2, g_rpe2);
    cudaGetSymbolAddress((void**)&ao,   g_ao);
    cudaGetSymbolAddress((void**)&y,    g_y);
    cudaGetSymbolAddress((void**)&h2,   g_h2);
    cudaGetSymbolAddress((void**)&mlp,  g_mlp);
    cudaGetSymbolAddress((void**)&wq,   g_wq);
    cudaGetSymbolAddress((void**)&wp,   g_wp);
    cudaGetSymbolAddress((void**)&ww1,  g_w1);
    cudaGetSymbolAddress((void**)&ww2,  g_w2);
    cudaGetSymbolAddress((void**)&qb,   g_qb);

    prep_kernel<<<1024, 256>>>(rel_index, rel_bias, rpe2,
                               qkv_w, proj_w, w1, w2, qkv_b,
                               wq, wp, ww1, ww2, qb);
    ln1_shift_kernel<<<TOK / 8, 256>>>(x, n1g, n1b, xw);
    gemm_bf16<0><<<dim3(TOK / 128, 3), 256>>>(xw, wq, qb, qkv, nullptr,
                                              TOK, 384, 128);
    attn_mma<<<dim3(NH, NWIN, 4), 256>>>(qkv, rpe2, ao);
    gemm_bf16<3><<<dim3(TOK / 128, 1), 256>>>(ao, wp, proj_b, y, x,
                                              TOK, 128, 128);
    ln2_kernel<<<TOK / 8, 256>>>(y, n2g, n2b, h2);
    gemm_bf16<1><<<dim3(TOK / 128, 4), 256>>>(h2, ww1, b1, mlp, nullptr,
                                              TOK, 512, 128);
    gemm_bf16<2><<<dim3(TOK / 128, 1), 256>>>(mlp, ww2, b2, out, y,
                                              TOK, 128, 512);
}

// round 14
// speedup vs baseline: 1.4475x; 1.1090x over previous
#include <cuda_runtime.h>
#include <cuda_bf16.h>
#include <math.h>
#include <stdint.h>

// Problem constants: B=1, D=16, H=64, W=64, C=128, WS=8, SS=4, NH=4, hd=32
#define TOK   65536
#define CCH   128
#define NWIN  128
#define WN    512
#define NH    4
#define HD    32
#define MLPH  512

typedef __nv_bfloat16 bf16;

// Scratch
__device__ bf16     g_xw [TOK * CCH];
__device__ bf16     g_qkv[TOK * 384];
__device__ uint32_t g_rpe2[NH * WN * 256];   // packed bf16 exp(rpe), chunk-major layout
__device__ bf16     g_ao [TOK * CCH];
__device__ float    g_y  [TOK * CCH];
__device__ bf16     g_h2 [TOK * CCH];
__device__ bf16     g_mlp[TOK * MLPH];
__device__ bf16     g_wq[384 * 128];
__device__ bf16     g_wp[128 * 128];
__device__ bf16     g_w1[512 * 128];
__device__ bf16     g_w2[128 * 512];
__device__ float    g_qb[384];

// ---------------------------------------------------------------------------
// Helpers
// ---------------------------------------------------------------------------
__device__ __forceinline__ uint32_t packbf(float lo, float hi) {
    uint32_t r;
    asm("cvt.rn.bf16x2.f32 %0, %1, %2;" : "=r"(r) : "f"(hi), "f"(lo));
    return r;
}
__device__ __forceinline__ float bflo(uint32_t u) { return __uint_as_float(u << 16); }
__device__ __forceinline__ float bfhi(uint32_t u) { return __uint_as_float(u & 0xffff0000u); }
__device__ __forceinline__ void mmabf(float* c, const uint32_t* a, const uint32_t* b) {
    asm volatile(
        "mma.sync.aligned.m16n8k16.row.col.f32.bf16.bf16.f32 "
        "{%0,%1,%2,%3},{%4,%5,%6,%7},{%8,%9},{%0,%1,%2,%3};"
        : "+f"(c[0]), "+f"(c[1]), "+f"(c[2]), "+f"(c[3])
        : "r"(a[0]), "r"(a[1]), "r"(a[2]), "r"(a[3]), "r"(b[0]), "r"(b[1]));
}
__device__ __forceinline__ void ldmx4(uint32_t* r, const void* p) {
    unsigned a = (unsigned)__cvta_generic_to_shared(p);
    asm volatile("ldmatrix.sync.aligned.m8n8.x4.shared.b16 {%0,%1,%2,%3}, [%4];"
        : "=r"(r[0]), "=r"(r[1]), "=r"(r[2]), "=r"(r[3]) : "r"(a));
}
__device__ __forceinline__ void ldmx4t(uint32_t* r, const void* p) {
    unsigned a = (unsigned)__cvta_generic_to_shared(p);
    asm volatile("ldmatrix.sync.aligned.m8n8.x4.trans.shared.b16 {%0,%1,%2,%3}, [%4];"
        : "=r"(r[0]), "=r"(r[1]), "=r"(r[2]), "=r"(r[3]) : "r"(a));
}
__device__ __forceinline__ void cpa16(void* dst, const void* src) {
    unsigned d = (unsigned)__cvta_generic_to_shared(dst);
    asm volatile("cp.async.cg.shared.global [%0], [%1], 16;" :: "r"(d), "l"(src));
}
#define CP_COMMIT() asm volatile("cp.async.commit_group;")
#define CP_WAIT(n)  asm volatile("cp.async.wait_group %0;" :: "n"(n))

// ---------------------------------------------------------------------------
// Fused prep: exp(rpe) packed-bf16 table (chunk-major permuted layout)
// + weight conversion (+ q scale fold).
// Output index for pair p (cols 2p,2p+1) of row n:
//   c4 = p&3, nj = (p>>2)&7, ci = p>>5  ->  o = n*256 + c4*64 + ci*8 + nj
// so each (row, c4, chunk) group of 8 nj values is contiguous (2x uint4).
// ---------------------------------------------------------------------------
__global__ void prep_kernel(const int* __restrict__ ri, const float* __restrict__ rb,
                            uint32_t* __restrict__ rpe2,
                            const float* __restrict__ wq, const float* __restrict__ wp,
                            const float* __restrict__ w1, const float* __restrict__ w2,
                            const float* __restrict__ qb,
                            bf16* __restrict__ oq, bf16* __restrict__ op,
                            bf16* __restrict__ o1, bf16* __restrict__ o2,
                            float* __restrict__ oqb)
{
    const float scale = 0.17677669529663687f;
    int i = blockIdx.x * 256 + threadIdx.x;
    if (i < 131072) {
        int n = i >> 8, p = i & 255;
        int r0 = ri[2 * i];
        int r1 = ri[2 * i + 1];
        int o = n * 256 + (p & 3) * 64 + (p >> 5) * 8 + ((p >> 2) & 7);
        #pragma unroll
        for (int h = 0; h < NH; h++)
            rpe2[h * 131072 + o] = packbf(__expf(rb[r0 * NH + h]),
                                          __expf(rb[r1 * NH + h]));
    }
    if (i < 384) oqb[i] = qb[i] * ((i < 128) ? scale : 1.f);
    if (i < 49152) {
        float v = wq[i] * (((i >> 7) < 128) ? scale : 1.f);
        oq[i] = __float2bfloat16(v);
    } else if (i < 65536)  op[i - 49152]  = __float2bfloat16(wp[i - 49152]);
    else if (i < 131072)   o1[i - 65536]  = __float2bfloat16(w1[i - 65536]);
    else if (i < 196608)   o2[i - 131072] = __float2bfloat16(w2[i - 131072]);
}

// ---------------------------------------------------------------------------
// LN1 + roll(-4,-4,-4) + window partition; bf16 out. One warp per token.
// ---------------------------------------------------------------------------
__global__ __launch_bounds__(256) void ln1_shift_kernel(
    const float* __restrict__ x, const float* __restrict__ g,
    const float* __restrict__ b, bf16* __restrict__ out)
{
    int m    = blockIdx.x * 8 + (threadIdx.x >> 5);
    int lane = threadIdx.x & 31;
    int win = m >> 9, nl = m & 511;
    int wd = win >> 6, wh = (win >> 3) & 7, ww = win & 7;
    int nd = nl >> 6,  nh = (nl >> 3) & 7,  nw = nl & 7;
    int d  = ((wd * 8 + nd) + 4) & 15;
    int hh = ((wh * 8 + nh) + 4) & 63;
    int w  = ((ww * 8 + nw) + 4) & 63;
    int t  = (d * 64 + hh) * 64 + w;

    float4 v = ((const float4*)(x + (size_t)t * CCH))[lane];
    float s  = v.x + v.y + v.z + v.w;
    float s2 = v.x * v.x + v.y * v.y + v.z * v.z + v.w * v.w;
    #pragma unroll
    for (int o = 16; o; o >>= 1) {
        s  += __shfl_xor_sync(0xffffffffu, s,  o);
        s2 += __shfl_xor_sync(0xffffffffu, s2, o);
    }
    float mean = s * (1.f / 128.f);
    float var  = s2 * (1.f / 128.f) - mean * mean;
    float inv  = rsqrtf(var + 1e-5f);
    float4 gg = ((const float4*)g)[lane];
    float4 bb = ((const float4*)b)[lane];
    uint32_t p0 = packbf((v.x - mean) * inv * gg.x + bb.x,
                         (v.y - mean) * inv * gg.y + bb.y);
    uint32_t p1 = packbf((v.z - mean) * inv * gg.z + bb.z,
                         (v.w - mean) * inv * gg.w + bb.w);
    *(uint2*)(out + (size_t)m * CCH + lane * 4) = make_uint2(p0, p1);
}

__global__ __launch_bounds__(256) void ln2_kernel(
    const float* __restrict__ x, const float* __restrict__ g,
    const float* __restrict__ b, bf16* __restrict__ out)
{
    int m    = blockIdx.x * 8 + (threadIdx.x >> 5);
    int lane = threadIdx.x & 31;
    float4 v = ((const float4*)(x + (size_t)m * CCH))[lane];
    float s  = v.x + v.y + v.z + v.w;
    float s2 = v.x * v.x + v.y * v.y + v.z * v.z + v.w * v.w;
    #pragma unroll
    for (int o = 16; o; o >>= 1) {
        s  += __shfl_xor_sync(0xffffffffu, s,  o);
        s2 += __shfl_xor_sync(0xffffffffu, s2, o);
    }
    float mean = s * (1.f / 128.f);
    float var  = s2 * (1.f / 128.f) - mean * mean;
    float inv  = rsqrtf(var + 1e-5f);
    float4 gg = ((const float4*)g)[lane];
    float4 bb = ((const float4*)b)[lane];
    uint32_t p0 = packbf((v.x - mean) * inv * gg.x + bb.x,
                         (v.y - mean) * inv * gg.y + bb.y);
    uint32_t p1 = packbf((v.z - mean) * inv * gg.z + bb.z,
                         (v.w - mean) * inv * gg.w + bb.w);
    *(uint2*)(out + (size_t)m * CCH + lane * 4) = make_uint2(p0, p1);
}

// ---------------------------------------------------------------------------
// bf16 GEMM (R11 measured-best form): C[M,N] = A[M,K] @ B[N,K]^T + epilogue.
// ---------------------------------------------------------------------------
template <int MODE>
__global__ __launch_bounds__(256) void gemm_bf16(
    const bf16* __restrict__ A, const bf16* __restrict__ B,
    const float* __restrict__ bias, void* __restrict__ Cv,
    const float* __restrict__ R, int M, int N, int K)
{
    __shared__ bf16 As[2][128][40];
    __shared__ bf16 Bs[2][128][40];
    int tid = threadIdx.x, lane = tid & 31, warp = tid >> 5;
    int bm = blockIdx.x * 128, bn = blockIdx.y * 128;
    int wm = (warp >> 2) * 64, wn = (warp & 3) * 32;
    int r4 = lane >> 2, c4 = lane & 3;

    float acc[4][4][4];
    #pragma unroll
    for (int i = 0; i < 4; i++)
        #pragma unroll
        for (int j = 0; j < 4; j++)
            #pragma unroll
            for (int c = 0; c < 4; c++) acc[i][j][c] = 0.f;

    int lr = tid >> 1, lc = (tid & 1) * 16;
    const bf16* Ag = A + (size_t)(bm + lr) * K + lc;
    const bf16* Bg = B + (size_t)(bn + lr) * K + lc;

    cpa16(&As[0][lr][lc],     Ag);
    cpa16(&As[0][lr][lc + 8], Ag + 8);
    cpa16(&Bs[0][lr][lc],     Bg);
    cpa16(&Bs[0][lr][lc + 8], Bg + 8);
    CP_COMMIT();

    int niter = K >> 5;
    #pragma unroll 1
    for (int it = 0; it < niter; it++) {
        int cur = it & 1;
        if (it + 1 < niter) {
            int nxt = cur ^ 1;
            int kt = (it + 1) * 32;
            cpa16(&As[nxt][lr][lc],     Ag + kt);
            cpa16(&As[nxt][lr][lc + 8], Ag + kt + 8);
            cpa16(&Bs[nxt][lr][lc],     Bg + kt);
            cpa16(&Bs[nxt][lr][lc + 8], Bg + kt + 8);
            CP_COMMIT();
            CP_WAIT(1);
        } else {
            CP_WAIT(0);
        }
        __syncthreads();
        #pragma unroll
        for (int k16 = 0; k16 < 32; k16 += 16) {
            uint32_t af[4][4], bfr[4][2];
            #pragma unroll
            for (int i = 0; i < 4; i++) {
                int r = wm + 16 * i;
                af[i][0] = *(const uint32_t*)&As[cur][r +     r4][k16 + 2 * c4];
                af[i][1] = *(const uint32_t*)&As[cur][r + 8 + r4][k16 + 2 * c4];
                af[i][2] = *(const uint32_t*)&As[cur][r +     r4][k16 + 2 * c4 + 8];
                af[i][3] = *(const uint32_t*)&As[cur][r + 8 + r4][k16 + 2 * c4 + 8];
            }
            #pragma unroll
            for (int j = 0; j < 4; j++) {
                int c = wn + 8 * j;
                bfr[j][0] = *(const uint32_t*)&Bs[cur][c + r4][k16 + 2 * c4];
                bfr[j][1] = *(const uint32_t*)&Bs[cur][c + r4][k16 + 2 * c4 + 8];
            }
            #pragma unroll
            for (int i = 0; i < 4; i++)
                #pragma unroll
                for (int j = 0; j < 4; j++)
                    mmabf(acc[i][j], af[i], bfr[j]);
        }
        __syncthreads();
    }

    #pragma unroll
    for (int i = 0; i < 4; i++) {
        #pragma unroll
        for (int h = 0; h < 2; h++) {
            int m = bm + wm + 16 * i + r4 + 8 * h;
            size_t trow = m;
            if (MODE == 3) {
                int win = m >> 9, nl = m & 511;
                int wd = win >> 6, wh = (win >> 3) & 7, ww = win & 7;
                int nd = nl >> 6,  nh = (nl >> 3) & 7,  nw = nl & 7;
                int d  = ((wd * 8 + nd) + 4) & 15;
                int hh = ((wh * 8 + nh) + 4) & 63;
                int w  = ((ww * 8 + nw) + 4) & 63;
                trow = (size_t)((d * 64 + hh) * 64 + w);
            }
            #pragma unroll
            for (int j = 0; j < 4; j++) {
                int c0 = bn + wn + 8 * j + 2 * c4;
                float v0 = acc[i][j][2 * h + 0] + bias[c0];
                float v1 = acc[i][j][2 * h + 1] + bias[c0 + 1];
                if (MODE == 0) {
                    *(uint32_t*)((bf16*)Cv + (size_t)m * N + c0) = packbf(v0, v1);
                } else if (MODE == 1) {
                    float g0 = 0.5f * v0 * (1.0f + erff(v0 * 0.70710678118654752f));
                    float g1 = 0.5f * v1 * (1.0f + erff(v1 * 0.70710678118654752f));
                    *(uint32_t*)((bf16*)Cv + (size_t)m * N + c0) = packbf(g0, g1);
                } else if (MODE == 2) {
                    float2 rr = *(const float2*)(R + (size_t)m * N + c0);
                    *(float2*)((float*)Cv + (size_t)m * N + c0) =
                        make_float2(v0 + rr.x, v1 + rr.y);
                } else {
                    float2 rr = *(const float2*)(R + trow * CCH + c0);
                    *(float2*)((float*)Cv + trow * CCH + c0) =
                        make_float2(v0 + rr.x, v1 + rr.y);
                }
            }
        }
    }
}

// ---------------------------------------------------------------------------
// bf16 tensor-core attention (R11 base): 3 blocks/SM, ldmatrix K fragments,
// chunk-major rpe2 -> 4x LDG.128 per chunk instead of 16x LDG.32.
// ---------------------------------------------------------------------------
__global__ __launch_bounds__(256, 3) void attn_mma(
    const bf16* __restrict__ qkv, const uint32_t* __restrict__ rpe2,
    bf16* __restrict__ out)
{
    __shared__ bf16 Ks[2][64][40];
    __shared__ bf16 Vs[2][64][40];
    __shared__ unsigned char regtab[512];

    int head = blockIdx.x, win = blockIdx.y, qt = blockIdx.z;
    int tid = threadIdx.x, lane = tid & 31, warp = tid >> 5;
    int r4 = lane >> 2, c4 = lane & 3;

    int wd = win >> 6, wh = (win >> 3) & 7, ww = win & 7;
    bool masked_win = (wd == 1) || (wh == 7) || (ww == 7);
    if (masked_win) {
        for (int n = tid; n < 512; n += 256) {
            int nd = n >> 6, nh = (n >> 3) & 7, nw = n & 7;
            int rd = (wd == 1) ? ((nd < 4) ? 1 : 2) : 0;
            int rh = (wh == 7) ? ((nh < 4) ? 1 : 2) : 0;
            int rw = (ww == 7) ? ((nw < 4) ? 1 : 2) : 0;
            regtab[n] = (unsigned char)(rd * 9 + rh * 3 + rw);
        }
    }

    int qr = qt * 128 + warp * 16;
    const bf16* qb = qkv + (size_t)(win * WN + qr) * 384 + head * HD;
    uint32_t qf[2][4];
    #pragma unroll
    for (int kb = 0; kb < 2; kb++) {
        qf[kb][0] = *(const uint32_t*)(qb + (size_t)r4       * 384 + kb * 16 + 2 * c4);
        qf[kb][1] = *(const uint32_t*)(qb + (size_t)(r4 + 8) * 384 + kb * 16 + 2 * c4);
        qf[kb][2] = *(const uint32_t*)(qb + (size_t)r4       * 384 + kb * 16 + 2 * c4 + 8);
        qf[kb][3] = *(const uint32_t*)(qb + (size_t)(r4 + 8) * 384 + kb * 16 + 2 * c4 + 8);
    }

    float o[4][4];
    #pragma unroll
    for (int j = 0; j < 4; j++)
        #pragma unroll
        for (int c = 0; c < 4; c++) o[j][c] = 0.f;
    float l0 = 0.f, l1 = 0.f;

    __syncthreads();
    int row0 = qr + r4, row1 = row0 + 8;
    int rr0 = 0, rr1 = 0;
    if (masked_win) { rr0 = regtab[row0]; rr1 = regtab[row1]; }
    // chunk-major rpe2: [head][row][c4][ci][nj] (nj contiguous)
    const uint32_t* rp0 = rpe2 + ((size_t)head << 17) + (size_t)row0 * 256 + c4 * 64;
    const uint32_t* rp1 = rpe2 + ((size_t)head << 17) + (size_t)row1 * 256 + c4 * 64;

    int ldrow = tid >> 2, ldsg = (tid & 3) * 8;
    int krow = (lane & 7) + 8 * ((lane >> 4) & 1);
    int kcol = ((lane >> 3) & 1) * 8;
    int vrow = (lane & 7) + ((lane >> 3) & 1) * 8;
    int vcol8 = ((lane >> 4) & 1) * 8;

    {
        const bf16* kbp = qkv + (size_t)(win * WN + ldrow) * 384 + 128 + head * HD + ldsg;
        cpa16(&Ks[0][ldrow][ldsg], kbp);
        cpa16(&Vs[0][ldrow][ldsg], kbp + 128);
        CP_COMMIT();
    }

    #pragma unroll 1
    for (int ci = 0; ci < 8; ci++) {
        int cur = ci & 1;
        if (ci + 1 < 8) {
            int nxt = cur ^ 1;
            const bf16* kbp = qkv + (size_t)(win * WN + (ci + 1) * 64 + ldrow) * 384
                              + 128 + head * HD + ldsg;
            cpa16(&Ks[nxt][ldrow][ldsg], kbp);
            cpa16(&Vs[nxt][ldrow][ldsg], kbp + 128);
            CP_COMMIT();
            CP_WAIT(1);
        } else {
            CP_WAIT(0);
        }
        __syncthreads();
        int c0 = ci * 64;

        // vectorized rpe loads for this chunk: 8 contiguous u32 per row
        uint32_t ra[8], rb8[8];
        *(uint4*)ra        = *(const uint4*)(rp0 + ci * 8);
        *(uint4*)(ra + 4)  = *(const uint4*)(rp0 + ci * 8 + 4);
        *(uint4*)rb8       = *(const uint4*)(rp1 + ci * 8);
        *(uint4*)(rb8 + 4) = *(const uint4*)(rp1 + ci * 8 + 4);

        #pragma unroll
        for (int kb = 0; kb < 4; kb++) {
            float s8[8];
            #pragma unroll
            for (int c = 0; c < 8; c++) s8[c] = 0.f;
            #pragma unroll
            for (int kq = 0; kq < 2; kq++) {
                uint32_t kf[4];
                ldmx4(kf, &Ks[cur][16 * kb + krow][kq * 16 + kcol]);
                mmabf(s8,     qf[kq], kf);
                mmabf(s8 + 4, qf[kq], kf + 2);
            }

            uint32_t pa[4];
            #pragma unroll
            for (int half = 0; half < 2; half++) {
                int nj = 2 * kb + half;
                float* s4 = s8 + 4 * half;
                uint32_t u0 = ra[nj];
                uint32_t u1 = rb8[nj];
                float e00 = __expf(s4[0]) * bflo(u0);
                float e01 = __expf(s4[1]) * bfhi(u0);
                float e10 = __expf(s4[2]) * bflo(u1);
                float e11 = __expf(s4[3]) * bfhi(u1);
                if (masked_win) {
                    int cc = c0 + nj * 8 + 2 * c4;
                    int rc0 = regtab[cc], rc1 = regtab[cc + 1];
                    e00 = (rr0 == rc0) ? e00 : 0.f;
                    e01 = (rr0 == rc1) ? e01 : 0.f;
                    e10 = (rr1 == rc0) ? e10 : 0.f;
                    e11 = (rr1 == rc1) ? e11 : 0.f;
                }
                l0 += e00 + e01;
                l1 += e10 + e11;
                pa[2 * half + 0] = packbf(e00, e01);
                pa[2 * half + 1] = packbf(e10, e11);
            }

            uint32_t vb[8];
            ldmx4t(vb,     &Vs[cur][kb * 16 + vrow][vcol8]);
            ldmx4t(vb + 4, &Vs[cur][kb * 16 + vrow][16 + vcol8]);
            mmabf(o[0], pa, vb);
            mmabf(o[1], pa, vb + 2);
            mmabf(o[2], pa, vb + 4);
            mmabf(o[3], pa, vb + 6);
        }
        __syncthreads();
    }

    l0 += __shfl_xor_sync(0xffffffffu, l0, 1);
    l0 += __shfl_xor_sync(0xffffffffu, l0, 2);
    l1 += __shfl_xor_sync(0xffffffffu, l1, 1);
    l1 += __shfl_xor_sync(0xffffffffu, l1, 2);
    float i0 = 1.f / l0, i1 = 1.f / l1;

    bf16* ob = out + (size_t)(win * WN + qr) * CCH + head * HD;
    #pragma unroll
    for (int dj = 0; dj < 4; dj++) {
        *(uint32_t*)(ob + (size_t)r4       * CCH + dj * 8 + 2 * c4) =
            packbf(o[dj][0] * i0, o[dj][1] * i0);
        *(uint32_t*)(ob + (size_t)(r4 + 8) * CCH + dj * 8 + 2 * c4) =
            packbf(o[dj][2] * i1, o[dj][3] * i1);
    }
}

// ---------------------------------------------------------------------------
extern "C" void kernel_launch(void* const* d_in, const int* in_sizes, int n_in,
                              void* d_out, int out_size)
{
    const float* x         = (const float*)d_in[0];
    const int*   rel_index = (const int*)  d_in[2];
    const float* rel_bias  = (const float*)d_in[3];
    const float* qkv_w     = (const float*)d_in[4];
    const float* qkv_b     = (const float*)d_in[5];
    const float* proj_w    = (const float*)d_in[6];
    const float* proj_b    = (const float*)d_in[7];
    const float* n1g       = (const float*)d_in[8];
    const float* n1b       = (const float*)d_in[9];
    const float* n2g       = (const float*)d_in[10];
    const float* n2b       = (const float*)d_in[11];
    const float* w1        = (const float*)d_in[12];
    const float* b1        = (const float*)d_in[13];
    const float* w2        = (const float*)d_in[14];
    const float* b2        = (const float*)d_in[15];
    float* out = (float*)d_out;

    bf16 *xw, *qkv, *ao, *h2, *mlp, *wq, *wp, *ww1, *ww2;
    float *y, *qb;
    uint32_t *rpe2;
    cudaGetSymbolAddress((void**)&xw,   g_xw);
    cudaGetSymbolAddress((void**)&qkv,  g_qkv);
    cudaGetSymbolAddress((void**)&rpe2, g_rpe2);
    cudaGetSymbolAddress((void**)&ao,   g_ao);
    cudaGetSymbolAddress((void**)&y,    g_y);
    cudaGetSymbolAddress((void**)&h2,   g_h2);
    cudaGetSymbolAddress((void**)&mlp,  g_mlp);
    cudaGetSymbolAddress((void**)&wq,   g_wq);
    cudaGetSymbolAddress((void**)&wp,   g_wp);
    cudaGetSymbolAddress((void**)&ww1,  g_w1);
    cudaGetSymbolAddress((void**)&ww2,  g_w2);
    cudaGetSymbolAddress((void**)&qb,   g_qb);

    prep_kernel<<<1024, 256>>>(rel_index, rel_bias, rpe2,
                               qkv_w, proj_w, w1, w2, qkv_b,
                               wq, wp, ww1, ww2, qb);
    ln1_shift_kernel<<<TOK / 8, 256>>>(x, n1g, n1b, xw);
    gemm_bf16<0><<<dim3(TOK / 128, 3), 256>>>(xw, wq, qb, qkv, nullptr,
                                              TOK, 384, 128);
    attn_mma<<<dim3(NH, NWIN, 4), 256>>>(qkv, rpe2, ao);
    gemm_bf16<3><<<dim3(TOK / 128, 1), 256>>>(ao, wp, proj_b, y, x,
                                              TOK, 128, 128);
    ln2_kernel<<<TOK / 8, 256>>>(y, n2g, n2b, h2);
    gemm_bf16<1><<<dim3(TOK / 128, 4), 256>>>(h2, ww1, b1, mlp, nullptr,
                                              TOK, 512, 128);
    gemm_bf16<2><<<dim3(TOK / 128, 1), 256>>>(mlp, ww2, b2, out, y,
                                              TOK, 128, 512);
}

// round 15
// speedup vs baseline: 1.5238x; 1.0527x over previous
#include <cuda_runtime.h>
#include <cuda_bf16.h>
#include <math.h>
#include <stdint.h>

// Problem constants: B=1, D=16, H=64, W=64, C=128, WS=8, SS=4, NH=4, hd=32
#define TOK   65536
#define CCH   128
#define NWIN  128
#define WN    512
#define NH    4
#define HD    32
#define MLPH  512

typedef __nv_bfloat16 bf16;

// Scratch
__device__ bf16     g_xw [TOK * CCH];
__device__ bf16     g_qkv[TOK * 384];
__device__ uint32_t g_rpe2[NH * WN * 256];   // packed bf16 pairs of exp(rpe)
__device__ bf16     g_ao [TOK * CCH];
__device__ float    g_y  [TOK * CCH];
__device__ bf16     g_h2 [TOK * CCH];
__device__ bf16     g_mlp[TOK * MLPH];
__device__ bf16     g_wq[384 * 128];
__device__ bf16     g_wp[128 * 128];
__device__ bf16     g_w1[512 * 128];
__device__ bf16     g_w2[128 * 512];
__device__ float    g_qb[384];

// ---------------------------------------------------------------------------
// Helpers
// ---------------------------------------------------------------------------
__device__ __forceinline__ uint32_t packbf(float lo, float hi) {
    uint32_t r;
    asm("cvt.rn.bf16x2.f32 %0, %1, %2;" : "=r"(r) : "f"(hi), "f"(lo));
    return r;
}
__device__ __forceinline__ float bflo(uint32_t u) { return __uint_as_float(u << 16); }
__device__ __forceinline__ float bfhi(uint32_t u) { return __uint_as_float(u & 0xffff0000u); }
__device__ __forceinline__ void mmabf(float* c, const uint32_t* a, const uint32_t* b) {
    asm volatile(
        "mma.sync.aligned.m16n8k16.row.col.f32.bf16.bf16.f32 "
        "{%0,%1,%2,%3},{%4,%5,%6,%7},{%8,%9},{%0,%1,%2,%3};"
        : "+f"(c[0]), "+f"(c[1]), "+f"(c[2]), "+f"(c[3])
        : "r"(a[0]), "r"(a[1]), "r"(a[2]), "r"(a[3]), "r"(b[0]), "r"(b[1]));
}
__device__ __forceinline__ void ldmx4(uint32_t* r, const void* p) {
    unsigned a = (unsigned)__cvta_generic_to_shared(p);
    asm volatile("ldmatrix.sync.aligned.m8n8.x4.shared.b16 {%0,%1,%2,%3}, [%4];"
        : "=r"(r[0]), "=r"(r[1]), "=r"(r[2]), "=r"(r[3]) : "r"(a));
}
__device__ __forceinline__ void ldmx4t(uint32_t* r, const void* p) {
    unsigned a = (unsigned)__cvta_generic_to_shared(p);
    asm volatile("ldmatrix.sync.aligned.m8n8.x4.trans.shared.b16 {%0,%1,%2,%3}, [%4];"
        : "=r"(r[0]), "=r"(r[1]), "=r"(r[2]), "=r"(r[3]) : "r"(a));
}
__device__ __forceinline__ void cpa16(void* dst, const void* src) {
    unsigned d = (unsigned)__cvta_generic_to_shared(dst);
    asm volatile("cp.async.cg.shared.global [%0], [%1], 16;" :: "r"(d), "l"(src));
}
#define CP_COMMIT() asm volatile("cp.async.commit_group;")
#define CP_WAIT(n)  asm volatile("cp.async.wait_group %0;" :: "n"(n))

// ---------------------------------------------------------------------------
// LN1 + roll + window partition, WITH prep fused in (blocks < 1024 also
// build the exp(rpe) table and bf16 weights). R11 rpe2 layout.
// ---------------------------------------------------------------------------
__global__ __launch_bounds__(256) void ln1_prep_kernel(
    const float* __restrict__ x, const float* __restrict__ g,
    const float* __restrict__ b, bf16* __restrict__ out,
    const int* __restrict__ ri, const float* __restrict__ rb,
    uint32_t* __restrict__ rpe2,
    const float* __restrict__ wq, const float* __restrict__ wp,
    const float* __restrict__ w1, const float* __restrict__ w2,
    const float* __restrict__ qb,
    bf16* __restrict__ oq, bf16* __restrict__ op,
    bf16* __restrict__ o1, bf16* __restrict__ o2,
    float* __restrict__ oqb)
{
    const float scale = 0.17677669529663687f;
    if (blockIdx.x < 1024) {
        int i = blockIdx.x * 256 + threadIdx.x;
        if (i < 131072) {
            int r0 = ri[2 * i];
            int r1 = ri[2 * i + 1];
            #pragma unroll
            for (int h = 0; h < NH; h++)
                rpe2[h * 131072 + i] = packbf(__expf(rb[r0 * NH + h]),
                                              __expf(rb[r1 * NH + h]));
        }
        if (i < 384) oqb[i] = qb[i] * ((i < 128) ? scale : 1.f);
        if (i < 49152) {
            float v = wq[i] * (((i >> 7) < 128) ? scale : 1.f);
            oq[i] = __float2bfloat16(v);
        } else if (i < 65536)  op[i - 49152]  = __float2bfloat16(wp[i - 49152]);
        else if (i < 131072)   o1[i - 65536]  = __float2bfloat16(w1[i - 65536]);
        else if (i < 196608)   o2[i - 131072] = __float2bfloat16(w2[i - 131072]);
    }

    int m    = blockIdx.x * 8 + (threadIdx.x >> 5);
    int lane = threadIdx.x & 31;
    int win = m >> 9, nl = m & 511;
    int wd = win >> 6, wh = (win >> 3) & 7, ww = win & 7;
    int nd = nl >> 6,  nh = (nl >> 3) & 7,  nw = nl & 7;
    int d  = ((wd * 8 + nd) + 4) & 15;
    int hh = ((wh * 8 + nh) + 4) & 63;
    int w  = ((ww * 8 + nw) + 4) & 63;
    int t  = (d * 64 + hh) * 64 + w;

    float4 v = ((const float4*)(x + (size_t)t * CCH))[lane];
    float s  = v.x + v.y + v.z + v.w;
    float s2 = v.x * v.x + v.y * v.y + v.z * v.z + v.w * v.w;
    #pragma unroll
    for (int o = 16; o; o >>= 1) {
        s  += __shfl_xor_sync(0xffffffffu, s,  o);
        s2 += __shfl_xor_sync(0xffffffffu, s2, o);
    }
    float mean = s * (1.f / 128.f);
    float var  = s2 * (1.f / 128.f) - mean * mean;
    float inv  = rsqrtf(var + 1e-5f);
    float4 gg = ((const float4*)g)[lane];
    float4 bb = ((const float4*)b)[lane];
    uint32_t p0 = packbf((v.x - mean) * inv * gg.x + bb.x,
                         (v.y - mean) * inv * gg.y + bb.y);
    uint32_t p1 = packbf((v.z - mean) * inv * gg.z + bb.z,
                         (v.w - mean) * inv * gg.w + bb.w);
    *(uint2*)(out + (size_t)m * CCH + lane * 4) = make_uint2(p0, p1);
}

// ---------------------------------------------------------------------------
// bf16 GEMM (R11 form): C[M,N] = A[M,K] @ B[N,K]^T + epilogue.
// MODE 0: +bias -> bf16        MODE 1: gelu(+bias) -> bf16
// MODE 2: +bias+R[m,n] -> f32
// MODE 3: +bias+R[t,n] scatter -> f32 y, PLUS fused LN2 -> bf16 h2
// ---------------------------------------------------------------------------
template <int MODE>
__global__ __launch_bounds__(256) void gemm_bf16(
    const bf16* __restrict__ A, const bf16* __restrict__ B,
    const float* __restrict__ bias, void* __restrict__ Cv,
    const float* __restrict__ R, int M, int N, int K,
    const float* __restrict__ lng, const float* __restrict__ lnb,
    bf16* __restrict__ H2)
{
    __shared__ bf16 As[2][128][40];
    __shared__ bf16 Bs[2][128][40];
    __shared__ float psum[(MODE == 3) ? 128 : 1][4];
    __shared__ float psq [(MODE == 3) ? 128 : 1][4];

    int tid = threadIdx.x, lane = tid & 31, warp = tid >> 5;
    int bm = blockIdx.x * 128, bn = blockIdx.y * 128;
    int wm = (warp >> 2) * 64, wn = (warp & 3) * 32;
    int r4 = lane >> 2, c4 = lane & 3;

    float acc[4][4][4];
    #pragma unroll
    for (int i = 0; i < 4; i++)
        #pragma unroll
        for (int j = 0; j < 4; j++)
            #pragma unroll
            for (int c = 0; c < 4; c++) acc[i][j][c] = 0.f;

    int lr = tid >> 1, lc = (tid & 1) * 16;
    const bf16* Ag = A + (size_t)(bm + lr) * K + lc;
    const bf16* Bg = B + (size_t)(bn + lr) * K + lc;

    cpa16(&As[0][lr][lc],     Ag);
    cpa16(&As[0][lr][lc + 8], Ag + 8);
    cpa16(&Bs[0][lr][lc],     Bg);
    cpa16(&Bs[0][lr][lc + 8], Bg + 8);
    CP_COMMIT();

    int niter = K >> 5;
    #pragma unroll 1
    for (int it = 0; it < niter; it++) {
        int cur = it & 1;
        if (it + 1 < niter) {
            int nxt = cur ^ 1;
            int kt = (it + 1) * 32;
            cpa16(&As[nxt][lr][lc],     Ag + kt);
            cpa16(&As[nxt][lr][lc + 8], Ag + kt + 8);
            cpa16(&Bs[nxt][lr][lc],     Bg + kt);
            cpa16(&Bs[nxt][lr][lc + 8], Bg + kt + 8);
            CP_COMMIT();
            CP_WAIT(1);
        } else {
            CP_WAIT(0);
        }
        __syncthreads();
        #pragma unroll
        for (int k16 = 0; k16 < 32; k16 += 16) {
            uint32_t af[4][4], bfr[4][2];
            #pragma unroll
            for (int i = 0; i < 4; i++) {
                int r = wm + 16 * i;
                af[i][0] = *(const uint32_t*)&As[cur][r +     r4][k16 + 2 * c4];
                af[i][1] = *(const uint32_t*)&As[cur][r + 8 + r4][k16 + 2 * c4];
                af[i][2] = *(const uint32_t*)&As[cur][r +     r4][k16 + 2 * c4 + 8];
                af[i][3] = *(const uint32_t*)&As[cur][r + 8 + r4][k16 + 2 * c4 + 8];
            }
            #pragma unroll
            for (int j = 0; j < 4; j++) {
                int c = wn + 8 * j;
                bfr[j][0] = *(const uint32_t*)&Bs[cur][c + r4][k16 + 2 * c4];
                bfr[j][1] = *(const uint32_t*)&Bs[cur][c + r4][k16 + 2 * c4 + 8];
            }
            #pragma unroll
            for (int i = 0; i < 4; i++)
                #pragma unroll
                for (int j = 0; j < 4; j++)
                    mmabf(acc[i][j], af[i], bfr[j]);
        }
        __syncthreads();
    }

    if (MODE == 3) {
        // pass 1: v = acc + bias + residual -> write y, fold into acc, partials
        #pragma unroll
        for (int i = 0; i < 4; i++) {
            #pragma unroll
            for (int h = 0; h < 2; h++) {
                int m = bm + wm + 16 * i + r4 + 8 * h;
                int win = m >> 9, nl = m & 511;
                int wd = win >> 6, wh = (win >> 3) & 7, ww = win & 7;
                int nd = nl >> 6,  nh = (nl >> 3) & 7,  nw = nl & 7;
                int d  = ((wd * 8 + nd) + 4) & 15;
                int hh = ((wh * 8 + nh) + 4) & 63;
                int w  = ((ww * 8 + nw) + 4) & 63;
                size_t trow = (size_t)((d * 64 + hh) * 64 + w);
                float rs = 0.f, rq = 0.f;
                #pragma unroll
                for (int j = 0; j < 4; j++) {
                    int c0 = wn + 8 * j + 2 * c4;
                    float2 rr = *(const float2*)(R + trow * CCH + c0);
                    float v0 = acc[i][j][2 * h + 0] + bias[c0]     + rr.x;
                    float v1 = acc[i][j][2 * h + 1] + bias[c0 + 1] + rr.y;
                    *(float2*)((float*)Cv + trow * CCH + c0) = make_float2(v0, v1);
                    acc[i][j][2 * h + 0] = v0;
                    acc[i][j][2 * h + 1] = v1;
                    rs += v0 + v1;
                    rq += v0 * v0 + v1 * v1;
                }
                rs += __shfl_xor_sync(0xffffffffu, rs, 1);
                rs += __shfl_xor_sync(0xffffffffu, rs, 2);
                rq += __shfl_xor_sync(0xffffffffu, rq, 1);
                rq += __shfl_xor_sync(0xffffffffu, rq, 2);
                if (c4 == 0) {
                    int lrow = wm + 16 * i + r4 + 8 * h;
                    psum[lrow][warp & 3] = rs;
                    psq [lrow][warp & 3] = rq;
                }
            }
        }
        __syncthreads();
        // pass 2: LN over each row, emit h2 (bf16)
        #pragma unroll
        for (int i = 0; i < 4; i++) {
            #pragma unroll
            for (int h = 0; h < 2; h++) {
                int lrow = wm + 16 * i + r4 + 8 * h;
                int m = bm + lrow;
                int win = m >> 9, nl = m & 511;
                int wd = win >> 6, wh = (win >> 3) & 7, ww = win & 7;
                int nd = nl >> 6,  nh = (nl >> 3) & 7,  nw = nl & 7;
                int d  = ((wd * 8 + nd) + 4) & 15;
                int hh = ((wh * 8 + nh) + 4) & 63;
                int w  = ((ww * 8 + nw) + 4) & 63;
                size_t trow = (size_t)((d * 64 + hh) * 64 + w);
                float s  = psum[lrow][0] + psum[lrow][1] + psum[lrow][2] + psum[lrow][3];
                float q  = psq [lrow][0] + psq [lrow][1] + psq [lrow][2] + psq [lrow][3];
                float mean = s * (1.f / 128.f);
                float var  = q * (1.f / 128.f) - mean * mean;
                float inv  = rsqrtf(var + 1e-5f);
                #pragma unroll
                for (int j = 0; j < 4; j++) {
                    int c0 = wn + 8 * j + 2 * c4;
                    float l0 = (acc[i][j][2 * h + 0] - mean) * inv * lng[c0]     + lnb[c0];
                    float l1 = (acc[i][j][2 * h + 1] - mean) * inv * lng[c0 + 1] + lnb[c0 + 1];
                    *(uint32_t*)(H2 + trow * CCH + c0) = packbf(l0, l1);
                }
            }
        }
        return;
    }

    #pragma unroll
    for (int i = 0; i < 4; i++) {
        #pragma unroll
        for (int h = 0; h < 2; h++) {
            int m = bm + wm + 16 * i + r4 + 8 * h;
            #pragma unroll
            for (int j = 0; j < 4; j++) {
                int c0 = bn + wn + 8 * j + 2 * c4;
                float v0 = acc[i][j][2 * h + 0] + bias[c0];
                float v1 = acc[i][j][2 * h + 1] + bias[c0 + 1];
                if (MODE == 0) {
                    *(uint32_t*)((bf16*)Cv + (size_t)m * N + c0) = packbf(v0, v1);
                } else if (MODE == 1) {
                    float g0 = 0.5f * v0 * (1.0f + erff(v0 * 0.70710678118654752f));
                    float g1 = 0.5f * v1 * (1.0f + erff(v1 * 0.70710678118654752f));
                    *(uint32_t*)((bf16*)Cv + (size_t)m * N + c0) = packbf(g0, g1);
                } else {
                    float2 rr = *(const float2*)(R + (size_t)m * N + c0);
                    *(float2*)((float*)Cv + (size_t)m * N + c0) =
                        make_float2(v0 + rr.x, v1 + rr.y);
                }
            }
        }
    }
}

// ---------------------------------------------------------------------------
// bf16 tensor-core attention (EXACT R11 measured-best): 3 blocks/SM,
// ldmatrix K fragments, scalar packed-bf16 exp(rpe) multiplies.
// ---------------------------------------------------------------------------
__global__ __launch_bounds__(256, 3) void attn_mma(
    const bf16* __restrict__ qkv, const uint32_t* __restrict__ rpe2,
    bf16* __restrict__ out)
{
    __shared__ bf16 Ks[2][64][40];
    __shared__ bf16 Vs[2][64][40];
    __shared__ unsigned char regtab[512];

    int head = blockIdx.x, win = blockIdx.y, qt = blockIdx.z;
    int tid = threadIdx.x, lane = tid & 31, warp = tid >> 5;
    int r4 = lane >> 2, c4 = lane & 3;

    int wd = win >> 6, wh = (win >> 3) & 7, ww = win & 7;
    bool masked_win = (wd == 1) || (wh == 7) || (ww == 7);
    if (masked_win) {
        for (int n = tid; n < 512; n += 256) {
            int nd = n >> 6, nh = (n >> 3) & 7, nw = n & 7;
            int rd = (wd == 1) ? ((nd < 4) ? 1 : 2) : 0;
            int rh = (wh == 7) ? ((nh < 4) ? 1 : 2) : 0;
            int rw = (ww == 7) ? ((nw < 4) ? 1 : 2) : 0;
            regtab[n] = (unsigned char)(rd * 9 + rh * 3 + rw);
        }
    }

    int qr = qt * 128 + warp * 16;
    const bf16* qb = qkv + (size_t)(win * WN + qr) * 384 + head * HD;
    uint32_t qf[2][4];
    #pragma unroll
    for (int kb = 0; kb < 2; kb++) {
        qf[kb][0] = *(const uint32_t*)(qb + (size_t)r4       * 384 + kb * 16 + 2 * c4);
        qf[kb][1] = *(const uint32_t*)(qb + (size_t)(r4 + 8) * 384 + kb * 16 + 2 * c4);
        qf[kb][2] = *(const uint32_t*)(qb + (size_t)r4       * 384 + kb * 16 + 2 * c4 + 8);
        qf[kb][3] = *(const uint32_t*)(qb + (size_t)(r4 + 8) * 384 + kb * 16 + 2 * c4 + 8);
    }

    float o[4][4];
    #pragma unroll
    for (int j = 0; j < 4; j++)
        #pragma unroll
        for (int c = 0; c < 4; c++) o[j][c] = 0.f;
    float l0 = 0.f, l1 = 0.f;

    __syncthreads();
    int row0 = qr + r4, row1 = row0 + 8;
    int rr0 = 0, rr1 = 0;
    if (masked_win) { rr0 = regtab[row0]; rr1 = regtab[row1]; }
    const uint32_t* rp0 = rpe2 + ((size_t)head << 17) + (size_t)row0 * 256 + c4;
    const uint32_t* rp1 = rpe2 + ((size_t)head << 17) + (size_t)row1 * 256 + c4;

    int ldrow = tid >> 2, ldsg = (tid & 3) * 8;
    int krow = (lane & 7) + 8 * ((lane >> 4) & 1);
    int kcol = ((lane >> 3) & 1) * 8;
    int vrow = (lane & 7) + ((lane >> 3) & 1) * 8;
    int vcol8 = ((lane >> 4) & 1) * 8;

    {
        const bf16* kbp = qkv + (size_t)(win * WN + ldrow) * 384 + 128 + head * HD + ldsg;
        cpa16(&Ks[0][ldrow][ldsg], kbp);
        cpa16(&Vs[0][ldrow][ldsg], kbp + 128);
        CP_COMMIT();
    }

    #pragma unroll 1
    for (int ci = 0; ci < 8; ci++) {
        int cur = ci & 1;
        if (ci + 1 < 8) {
            int nxt = cur ^ 1;
            const bf16* kbp = qkv + (size_t)(win * WN + (ci + 1) * 64 + ldrow) * 384
                              + 128 + head * HD + ldsg;
            cpa16(&Ks[nxt][ldrow][ldsg], kbp);
            cpa16(&Vs[nxt][ldrow][ldsg], kbp + 128);
            CP_COMMIT();
            CP_WAIT(1);
        } else {
            CP_WAIT(0);
        }
        __syncthreads();
        int c0 = ci * 64;

        #pragma unroll
        for (int kb = 0; kb < 4; kb++) {
            float s8[8];
            #pragma unroll
            for (int c = 0; c < 8; c++) s8[c] = 0.f;
            #pragma unroll
            for (int kq = 0; kq < 2; kq++) {
                uint32_t kf[4];
                ldmx4(kf, &Ks[cur][16 * kb + krow][kq * 16 + kcol]);
                mmabf(s8,     qf[kq], kf);
                mmabf(s8 + 4, qf[kq], kf + 2);
            }

            uint32_t pa[4];
            #pragma unroll
            for (int half = 0; half < 2; half++) {
                int nj = 2 * kb + half;
                float* s4 = s8 + 4 * half;
                uint32_t u0 = rp0[ci * 32 + nj * 4];
                uint32_t u1 = rp1[ci * 32 + nj * 4];
                float e00 = __expf(s4[0]) * bflo(u0);
                float e01 = __expf(s4[1]) * bfhi(u0);
                float e10 = __expf(s4[2]) * bflo(u1);
                float e11 = __expf(s4[3]) * bfhi(u1);
                if (masked_win) {
                    int cc = c0 + nj * 8 + 2 * c4;
                    int rc0 = regtab[cc], rc1 = regtab[cc + 1];
                    e00 = (rr0 == rc0) ? e00 : 0.f;
                    e01 = (rr0 == rc1) ? e01 : 0.f;
                    e10 = (rr1 == rc0) ? e10 : 0.f;
                    e11 = (rr1 == rc1) ? e11 : 0.f;
                }
                l0 += e00 + e01;
                l1 += e10 + e11;
                pa[2 * half + 0] = packbf(e00, e01);
                pa[2 * half + 1] = packbf(e10, e11);
            }

            uint32_t vb[8];
            ldmx4t(vb,     &Vs[cur][kb * 16 + vrow][vcol8]);
            ldmx4t(vb + 4, &Vs[cur][kb * 16 + vrow][16 + vcol8]);
            mmabf(o[0], pa, vb);
            mmabf(o[1], pa, vb + 2);
            mmabf(o[2], pa, vb + 4);
            mmabf(o[3], pa, vb + 6);
        }
        __syncthreads();
    }

    l0 += __shfl_xor_sync(0xffffffffu, l0, 1);
    l0 += __shfl_xor_sync(0xffffffffu, l0, 2);
    l1 += __shfl_xor_sync(0xffffffffu, l1, 1);
    l1 += __shfl_xor_sync(0xffffffffu, l1, 2);
    float i0 = 1.f / l0, i1 = 1.f / l1;

    bf16* ob = out + (size_t)(win * WN + qr) * CCH + head * HD;
    #pragma unroll
    for (int dj = 0; dj < 4; dj++) {
        *(uint32_t*)(ob + (size_t)r4       * CCH + dj * 8 + 2 * c4) =
            packbf(o[dj][0] * i0, o[dj][1] * i0);
        *(uint32_t*)(ob + (size_t)(r4 + 8) * CCH + dj * 8 + 2 * c4) =
            packbf(o[dj][2] * i1, o[dj][3] * i1);
    }
}

// ---------------------------------------------------------------------------
extern "C" void kernel_launch(void* const* d_in, const int* in_sizes, int n_in,
                              void* d_out, int out_size)
{
    const float* x         = (const float*)d_in[0];
    const int*   rel_index = (const int*)  d_in[2];
    const float* rel_bias  = (const float*)d_in[3];
    const float* qkv_w     = (const float*)d_in[4];
    const float* qkv_b     = (const float*)d_in[5];
    const float* proj_w    = (const float*)d_in[6];
    const float* proj_b    = (const float*)d_in[7];
    const float* n1g       = (const float*)d_in[8];
    const float* n1b       = (const float*)d_in[9];
    const float* n2g       = (const float*)d_in[10];
    const float* n2b       = (const float*)d_in[11];
    const float* w1        = (const float*)d_in[12];
    const float* b1        = (const float*)d_in[13];
    const float* w2        = (const float*)d_in[14];
    const float* b2        = (const float*)d_in[15];
    float* out = (float*)d_out;

    bf16 *xw, *qkv, *ao, *h2, *mlp, *wq, *wp, *ww1, *ww2;
    float *y, *qb;
    uint32_t *rpe2;
    cudaGetSymbolAddress((void**)&xw,   g_xw);
    cudaGetSymbolAddress((void**)&qkv,  g_qkv);
    cudaGetSymbolAddress((void**)&rpe2, g_rpe2);
    cudaGetSymbolAddress((void**)&ao,   g_ao);
    cudaGetSymbolAddress((void**)&y,    g_y);
    cudaGetSymbolAddress((void**)&h2,   g_h2);
    cudaGetSymbolAddress((void**)&mlp,  g_mlp);
    cudaGetSymbolAddress((void**)&wq,   g_wq);
    cudaGetSymbolAddress((void**)&wp,   g_wp);
    cudaGetSymbolAddress((void**)&ww1,  g_w1);
    cudaGetSymbolAddress((void**)&ww2,  g_w2);
    cudaGetSymbolAddress((void**)&qb,   g_qb);

    ln1_prep_kernel<<<TOK / 8, 256>>>(x, n1g, n1b, xw,
                                      rel_index, rel_bias, rpe2,
                                      qkv_w, proj_w, w1, w2, qkv_b,
                                      wq, wp, ww1, ww2, qb);
    gemm_bf16<0><<<dim3(TOK / 128, 3), 256>>>(xw, wq, qb, qkv, nullptr,
                                              TOK, 384, 128, nullptr, nullptr, nullptr);
    attn_mma<<<dim3(NH, NWIN, 4), 256>>>(qkv, rpe2, ao);
    // proj + residual + fused LN2 (writes y and h2)
    gemm_bf16<3><<<dim3(TOK / 128, 1), 256>>>(ao, wp, proj_b, y, x,
                                              TOK, 128, 128, n2g, n2b, h2);
    gemm_bf16<1><<<dim3(TOK / 128, 4), 256>>>(h2, ww1, b1, mlp, nullptr,
                                              TOK, 512, 128, nullptr, nullptr, nullptr);
    gemm_bf16<2><<<dim3(TOK / 128, 1), 256>>>(mlp, ww2, b2, out, y,
                                              TOK, 128, 512, nullptr, nullptr, nullptr);
}